// round 12
// baseline (speedup 1.0000x reference)
#include <cuda_runtime.h>
#include <cuda_bf16.h>
#include <cstdint>

#define Bdim 64
#define Tdim 512
#define Idim 512
#define Hdim 1024
#define Gdim 4096
#define NCTA 128

typedef unsigned long long ull;

// ---------------- device globals (allocation-free scratch) ----------------------
__device__ float g_gates_x[(size_t)Tdim * Bdim * Gdim];          // [t][b][4096]
// pre-swizzled chunk images: row*256B + ((seg ^ (row&7))<<4)
__device__ __align__(16) unsigned char g_h_img[2][2][8][16384];  // [pp][plane][kc][64 rows]
__device__ __align__(16) unsigned char g_w_img[NCTA][2][8][8192]; // [jb][plane][kc][32 rows]
__device__ unsigned g_h_flags[NCTA];                             // barrier flags

// ---------------- helpers --------------------------------------------------------
__device__ __forceinline__ uint32_t smem_u32(const void* p) {
    uint32_t a;
    asm("{ .reg .u64 t; cvta.to.shared.u64 t, %1; cvt.u32.u64 %0, t; }" : "=r"(a) : "l"(p));
    return a;
}
__device__ __forceinline__ void mbar_init(uint32_t a, uint32_t cnt) {
    asm volatile("mbarrier.init.shared.b64 [%0], %1;" :: "r"(a), "r"(cnt) : "memory");
}
__device__ __forceinline__ void mbar_expect(uint32_t a, uint32_t tx) {
    asm volatile("mbarrier.arrive.expect_tx.shared.b64 _, [%0], %1;" :: "r"(a), "r"(tx) : "memory");
}
__device__ __forceinline__ void mbar_wait(uint32_t a, uint32_t parity) {
    asm volatile(
        "{\n\t.reg .pred P;\n\t"
        "WL_%=:\n\t"
        "mbarrier.try_wait.parity.acquire.cta.shared::cta.b64 P, [%0], %1, 0x989680;\n\t"
        "@P bra WD_%=;\n\t"
        "bra WL_%=;\n\t"
        "WD_%=:\n\t}"
        :: "r"(a), "r"(parity) : "memory");
}
__device__ __forceinline__ void bulk_g2s(uint32_t dst, const void* src, uint32_t bytes,
                                         uint32_t mbar) {
    asm volatile(
        "cp.async.bulk.shared::cta.global.mbarrier::complete_tx::bytes [%0], [%1], %2, [%3];"
        :: "r"(dst), "l"(src), "r"(bytes), "r"(mbar) : "memory");
}
__device__ __forceinline__ void ldm_x4(uint32_t& r0, uint32_t& r1, uint32_t& r2,
                                       uint32_t& r3, uint32_t addr) {
    asm volatile("ldmatrix.sync.aligned.m8n8.x4.shared.b16 {%0,%1,%2,%3}, [%4];"
                 : "=r"(r0), "=r"(r1), "=r"(r2), "=r"(r3) : "r"(addr));
}
__device__ __forceinline__ void mma_bf16(float* c, uint32_t a0, uint32_t a1,
                                         uint32_t a2, uint32_t a3,
                                         uint32_t b0, uint32_t b1) {
    asm volatile(
        "mma.sync.aligned.m16n8k16.row.col.f32.bf16.bf16.f32 "
        "{%0,%1,%2,%3}, {%4,%5,%6,%7}, {%8,%9}, {%0,%1,%2,%3};"
        : "+f"(c[0]), "+f"(c[1]), "+f"(c[2]), "+f"(c[3])
        : "r"(a0), "r"(a1), "r"(a2), "r"(a3), "r"(b0), "r"(b1));
}
__device__ __forceinline__ ull pack2(float x, float y) {
    ull r; asm("mov.b64 %0, {%1,%2};" : "=l"(r) : "f"(x), "f"(y)); return r;
}
__device__ __forceinline__ void unpack2(ull v, float& x, float& y) {
    asm("mov.b64 {%0,%1}, %2;" : "=f"(x), "=f"(y) : "l"(v));
}
__device__ __forceinline__ void ffma2(ull& d, ull a, ull b) {
    asm("fma.rn.f32x2 %0, %1, %2, %0;" : "+l"(d) : "l"(a), "l"(b));
}
__device__ __forceinline__ float sigm_(float x) {
    return __fdividef(1.0f, 1.0f + __expf(-x));
}
__device__ __forceinline__ float tanh_(float x) {
    return 1.0f - __fdividef(2.0f, __expf(2.0f * x) + 1.0f);
}

// ---------------- init ------------------------------------------------------------
__global__ void init_state(float* __restrict__ out) {
    int i = blockIdx.x * blockDim.x + threadIdx.x;  // 65536 threads
    ((uint32_t*)g_h_img[0])[i] = 0u;   // zero pp=0 h image (256 KB)
    out[i] = 0.0f;
    if (i < NCTA) g_h_flags[i] = 0u;
}

// ---------------- W_hh -> pre-swizzled per-CTA chunk images -------------------------
__global__ __launch_bounds__(256) void w_prep(const float* __restrict__ Whh) {
    int bid = blockIdx.x;            // 4096 = 128 jb x 32 nl
    int jb = bid >> 5;
    int nl = bid & 31;
    int grow = (nl >> 3) * Hdim + jb * 8 + (nl & 7);
    const float* src = Whh + (size_t)grow * Hdim;
#pragma unroll
    for (int q = 0; q < 4; q++) {
        int k = q * 256 + threadIdx.x;
        float w = src[k];
        __nv_bfloat16 hi = __float2bfloat16(w);
        __nv_bfloat16 lo = __float2bfloat16(w - __bfloat162float(hi));
        int kc = k >> 7;
        int kk = k & 127;
        int seg = kk >> 3;
        uint32_t off = (uint32_t)(nl * 256 + ((seg ^ (nl & 7)) << 4) + (kk & 7) * 2);
        *(__nv_bfloat16*)(&g_w_img[jb][0][kc][off]) = hi;
        *(__nv_bfloat16*)(&g_w_img[jb][1][kc][off]) = lo;
    }
}

// ---------------- GEMM1 (fp32x2 SIMT, proven) ---------------------------------------
__global__ __launch_bounds__(256) void gates_x_gemm(
    const float* __restrict__ seq, const float* __restrict__ Wih,
    const float* __restrict__ bih, const float* __restrict__ bhh) {
    __shared__ float As[8][132];
    __shared__ float Bs[8][132];

    const int tid = threadIdx.x;
    const int tx = tid & 15;
    const int ty = tid >> 4;
    const int m0 = blockIdx.y * 128;
    const int n0 = blockIdx.x * 128;

    const int lr = tid >> 1;
    const int lk = (tid & 1) * 4;
    const float* aptr = seq + (size_t)(m0 + lr) * Idim + lk;
    const float* bptr = Wih + (size_t)(n0 + lr) * Idim + lk;

    ull acc[8][4];
#pragma unroll
    for (int i = 0; i < 8; i++)
#pragma unroll
        for (int j = 0; j < 4; j++) acc[i][j] = 0ull;

    for (int k0 = 0; k0 < Idim; k0 += 8) {
        float4 av = *(const float4*)(aptr + k0);
        float4 bv = *(const float4*)(bptr + k0);
        As[lk + 0][lr] = av.x; As[lk + 1][lr] = av.y;
        As[lk + 2][lr] = av.z; As[lk + 3][lr] = av.w;
        Bs[lk + 0][lr] = bv.x; Bs[lk + 1][lr] = bv.y;
        Bs[lk + 2][lr] = bv.z; Bs[lk + 3][lr] = bv.w;
        __syncthreads();
#pragma unroll
        for (int k = 0; k < 8; k++) {
            float4 a0 = *(const float4*)&As[k][ty * 8];
            float4 a1 = *(const float4*)&As[k][ty * 8 + 4];
            ull pb0 = *(const ull*)&Bs[k][tx * 8 + 0];
            ull pb1 = *(const ull*)&Bs[k][tx * 8 + 2];
            ull pb2 = *(const ull*)&Bs[k][tx * 8 + 4];
            ull pb3 = *(const ull*)&Bs[k][tx * 8 + 6];
            float am[8] = {a0.x, a0.y, a0.z, a0.w, a1.x, a1.y, a1.z, a1.w};
#pragma unroll
            for (int i = 0; i < 8; i++) {
                ull pa = pack2(am[i], am[i]);
                ffma2(acc[i][0], pa, pb0);
                ffma2(acc[i][1], pa, pb1);
                ffma2(acc[i][2], pa, pb2);
                ffma2(acc[i][3], pa, pb3);
            }
        }
        __syncthreads();
    }

#pragma unroll
    for (int i = 0; i < 8; i++) {
        int m = m0 + ty * 8 + i;
        int b = m >> 9;        // T = 512
        int t = m & 511;
        float* orow = g_gates_x + (size_t)(t * Bdim + b) * Gdim;
#pragma unroll
        for (int j = 0; j < 4; j++) {
            int n = n0 + tx * 8 + j * 2;
            float x, y; unpack2(acc[i][j], x, y);
            orow[n]     = x + bih[n]     + bhh[n];
            orow[n + 1] = y + bih[n + 1] + bhh[n + 1];
        }
    }
}

// ---------------- persistent HMMA recurrence (flag barrier, overlapped gx) ----------
#define OFF_W 0                          // [plane][kc][8192] = 131072 B
#define OFF_H 131072                     // 2 stages x (Ahi 16384 | Alo 16384)
#define OFF_PRE (OFF_H + 2 * 32768)      // 196608
#define OFF_MBAR (OFF_PRE + 64 * 36 * 4) // 205824 (mb_h0, mb_h1, mb_w)
#define SMEM_BYTES (OFF_MBAR + 64)       // 205888

__global__ __launch_bounds__(256, 1) void lstm_persist(
    const int* __restrict__ lens, float* __restrict__ out) {
    extern __shared__ unsigned char smem[];
    const uint32_t sb = smem_u32(smem);
    float* pre = (float*)(smem + OFF_PRE);        // [64][36]
    const uint32_t mb_h = sb + OFF_MBAR;          // 2 stage mbars, 8B apart
    const uint32_t mb_w = sb + OFF_MBAR + 16;

    const int tid = threadIdx.x;
    const int lane = tid & 31;
    const int w = tid >> 5;
    const int mt = w & 3;
    const int nh = w >> 2;
    const int jb = blockIdx.x;
    const int j0 = jb * 8;

    if (tid == 0) {
        mbar_init(mb_h, 1);
        mbar_init(mb_h + 8, 1);
        mbar_init(mb_w, 1);
    }
    __syncthreads();

    // ---- one-time: W slice (both planes) -> smem via 2 bulk copies
    if (tid == 0) {
        mbar_expect(mb_w, 131072);
        bulk_g2s(sb + OFF_W,         &g_w_img[jb][0][0][0], 65536, mb_w);
        bulk_g2s(sb + OFF_W + 65536, &g_w_img[jb][1][0][0], 65536, mb_w);
    }
    mbar_wait(mb_w, 0);

    // ---- per-lane fragment addressing (proven rounds 10-11)
    const int rowa = mt * 16 + (lane & 7) + ((lane >> 3) & 1) * 8;   // A row (batch)
    const int selA = (lane >> 4) & 1;
    const int xa = rowa & 7;
    const uint32_t a_base = (uint32_t)(rowa * 256);
    const int rowb = nh * 16 + (lane & 7) + ((lane >> 4) & 1) * 8;   // B row (gate col)
    const int selB = (lane >> 3) & 1;
    const int xb = rowb & 7;
    const uint32_t b_base = (uint32_t)(rowb * 256);

    // ---- persistent per-thread state (threads 0-63: b = tid)
    float cst[8];
#pragma unroll
    for (int q = 0; q < 8; q++) cst[q] = 0.0f;
    const int lb = (tid < 64) ? lens[tid] : 0;

    // gates_x prefetch helper (threads 0-63)
    float gx[32];
    auto gx_prefetch = [&](int tt) {
        const float* gxb = g_gates_x + ((size_t)tt * Bdim + tid) * Gdim + j0;
#pragma unroll
        for (int g = 0; g < 4; g++) {
            float4 v0 = *(const float4*)(gxb + g * Hdim);
            float4 v1 = *(const float4*)(gxb + g * Hdim + 4);
            gx[g * 8 + 0] = v0.x; gx[g * 8 + 1] = v0.y;
            gx[g * 8 + 2] = v0.z; gx[g * 8 + 3] = v0.w;
            gx[g * 8 + 4] = v1.x; gx[g * 8 + 5] = v1.y;
            gx[g * 8 + 6] = v1.z; gx[g * 8 + 7] = v1.w;
        }
    };
    if (tid < 64) gx_prefetch(0);

    // epilogue h-image addressing
    const int jc = j0 >> 7;
    const int sg = (j0 & 127) >> 3;

    for (int t = 0; t < Tdim; t++) {
        const int pp = t & 1;

        // bulk issuer: chunk kc of this step -> stage (t*8+kc)&1
        auto issue_chunk = [&](int kc) {
            int n = t * 8 + kc;
            int s = n & 1;
            uint32_t dst = sb + OFF_H + s * 32768;
            uint32_t mb = mb_h + s * 8;
            mbar_expect(mb, 32768);
            bulk_g2s(dst,         &g_h_img[pp][0][kc][0], 16384, mb);
            bulk_g2s(dst + 16384, &g_h_img[pp][1][kc][0], 16384, mb);
        };

        if (tid == 0) { issue_chunk(0); issue_chunk(1); }

        float C0[2][4], C1[2][4], C2[2][4];
#pragma unroll
        for (int nt = 0; nt < 2; nt++)
#pragma unroll
            for (int k = 0; k < 4; k++) { C0[nt][k] = 0.f; C1[nt][k] = 0.f; C2[nt][k] = 0.f; }

        for (int kc = 0; kc < 8; kc++) {
            int n = t * 8 + kc;
            mbar_wait(mb_h + (n & 1) * 8, (n >> 1) & 1);

            uint32_t abase = sb + OFF_H + (n & 1) * 32768 + a_base;
            uint32_t bbase = sb + OFF_W + kc * 8192 + b_base;
#pragma unroll
            for (int ks = 0; ks < 8; ks++) {
                uint32_t aoff = abase + (uint32_t)((((2 * ks + selA) ^ xa)) << 4);
                uint32_t boff = bbase + (uint32_t)((((2 * ks + selB) ^ xb)) << 4);
                uint32_t ah0, ah1, ah2, ah3, al0, al1, al2, al3;
                ldm_x4(ah0, ah1, ah2, ah3, aoff);
                ldm_x4(al0, al1, al2, al3, aoff + 16384);
                uint32_t p0, p1, p2, p3;          // B hi
                ldm_x4(p0, p1, p2, p3, boff);
                uint32_t s0, s1, s2, s3;          // B lo
                ldm_x4(s0, s1, s2, s3, boff + 65536);

                mma_bf16(C0[0], ah0, ah1, ah2, ah3, p0, p1);
                mma_bf16(C0[1], ah0, ah1, ah2, ah3, p2, p3);
                mma_bf16(C1[0], ah0, ah1, ah2, ah3, s0, s1);
                mma_bf16(C1[1], ah0, ah1, ah2, ah3, s2, s3);
                mma_bf16(C2[0], al0, al1, al2, al3, p0, p1);
                mma_bf16(C2[1], al0, al1, al2, al3, p2, p3);
            }
            __syncthreads();                      // reads of stage n&1 retired
            if (tid == 0 && kc + 2 < 8) issue_chunk(kc + 2);
        }

        // merge split terms -> pre[64][36]
        {
            int g = lane >> 2, t2 = (lane & 3) * 2;
            int m = mt * 16 + g;
#pragma unroll
            for (int nt = 0; nt < 2; nt++) {
                float s0 = C0[nt][0] + C1[nt][0] + C2[nt][0];
                float s1 = C0[nt][1] + C1[nt][1] + C2[nt][1];
                float s2 = C0[nt][2] + C1[nt][2] + C2[nt][2];
                float s3 = C0[nt][3] + C1[nt][3] + C2[nt][3];
                int nn = nh * 16 + nt * 8 + t2;
                *(float2*)&pre[m * 36 + nn]       = make_float2(s0, s1);
                *(float2*)&pre[(m + 8) * 36 + nn] = make_float2(s2, s3);
            }
        }
        __syncthreads();

        // pointwise LSTM cell (threads 0-63, b = tid)
        if (tid < 64) {
            int b = tid;
            float hn[8];
            unsigned short hu[8], lu[8];
#pragma unroll
            for (int jj = 0; jj < 8; jj++) {
                float xi = pre[b * 36 + jj]      + gx[jj];
                float xf = pre[b * 36 + 8 + jj]  + gx[8 + jj];
                float xg = pre[b * 36 + 16 + jj] + gx[16 + jj];
                float xo = pre[b * 36 + 24 + jj] + gx[24 + jj];
                float i_ = sigm_(xi), f_ = sigm_(xf), g_ = tanh_(xg), o_ = sigm_(xo);
                float cn = f_ * cst[jj] + i_ * g_;
                cst[jj] = cn;
                float h = o_ * tanh_(cn);
                hn[jj] = h;
                __nv_bfloat16 hh = __float2bfloat16(h);
                __nv_bfloat16 hl = __float2bfloat16(h - __bfloat162float(hh));
                hu[jj] = __bfloat16_as_ushort(hh);
                lu[jj] = __bfloat16_as_ushort(hl);
            }
            uint4 vh, vl;
            vh.x = (uint32_t)hu[0] | ((uint32_t)hu[1] << 16);
            vh.y = (uint32_t)hu[2] | ((uint32_t)hu[3] << 16);
            vh.z = (uint32_t)hu[4] | ((uint32_t)hu[5] << 16);
            vh.w = (uint32_t)hu[6] | ((uint32_t)hu[7] << 16);
            vl.x = (uint32_t)lu[0] | ((uint32_t)lu[1] << 16);
            vl.y = (uint32_t)lu[2] | ((uint32_t)lu[3] << 16);
            vl.z = (uint32_t)lu[4] | ((uint32_t)lu[5] << 16);
            vl.w = (uint32_t)lu[6] | ((uint32_t)lu[7] << 16);

            int pp1 = pp ^ 1;
            uint32_t hoff = (uint32_t)(b * 256 + ((sg ^ (b & 7)) << 4));
            *(uint4*)(&g_h_img[pp1][0][jc][hoff]) = vh;
            *(uint4*)(&g_h_img[pp1][1][jc][hoff]) = vl;

            if (lb > t) {
                float* ob = out + (size_t)b * Hdim + j0;
                *(float4*)(ob)     = make_float4(hn[0], hn[1], hn[2], hn[3]);
                *(float4*)(ob + 4) = make_float4(hn[4], hn[5], hn[6], hn[7]);
            }
            // make generic-proxy h stores visible to next step's async-proxy bulk reads
            asm volatile("fence.proxy.async;" ::: "memory");

            // prefetch NEXT step's gates_x now; latency hides under the barrier spin
            gx_prefetch(t + 1 < Tdim ? t + 1 : t);
        }

        // ---- distributed-flag grid barrier -----------------------------------------
        __syncthreads();
        if (tid == 0) {
            __threadfence();                       // release h-image writes
            *((volatile unsigned*)&g_h_flags[jb]) = (unsigned)(t + 1);
        }
        if (tid < NCTA) {
            while (*((volatile unsigned*)&g_h_flags[tid]) < (unsigned)(t + 1)) { }
        }
        __syncthreads();
    }
}

// ---------------- launch ------------------------------------------------------------
extern "C" void kernel_launch(void* const* d_in, const int* in_sizes, int n_in,
                              void* d_out, int out_size) {
    const float* seq   = (const float*)d_in[0];
    const int*   lensp = (const int*)d_in[1];
    const float* Wih   = (const float*)d_in[2];
    const float* Whh   = (const float*)d_in[3];
    const float* bih   = (const float*)d_in[4];
    const float* bhh   = (const float*)d_in[5];
    float* out = (float*)d_out;

    cudaFuncSetAttribute(lstm_persist,
                         cudaFuncAttributeMaxDynamicSharedMemorySize, SMEM_BYTES);

    init_state<<<256, 256>>>(out);
    w_prep<<<4096, 256>>>(Whh);

    dim3 g1(Gdim / 128, (Bdim * Tdim) / 128);
    gates_x_gemm<<<g1, 256>>>(seq, Wih, bih, bhh);

    lstm_persist<<<NCTA, 256, SMEM_BYTES>>>(lensp, out);
}

// round 13
// speedup vs baseline: 1.3796x; 1.3796x over previous
#include <cuda_runtime.h>
#include <cuda_bf16.h>
#include <cstdint>

#define Bdim 64
#define Tdim 512
#define Idim 512
#define Hdim 1024
#define Gdim 4096
#define NCTA 128

typedef unsigned long long ull;

// ---------------- device globals (allocation-free scratch) ----------------------
__device__ float g_gates_x[(size_t)Tdim * Bdim * Gdim];          // [t][b][4096]
// pre-swizzled chunk images: row*256B + ((seg ^ (row&7))<<4)
__device__ __align__(16) unsigned char g_h_img[2][2][8][16384];  // [pp][plane][kc][64 rows]
__device__ __align__(16) unsigned char g_w_img[NCTA][2][8][8192]; // [jb][plane][kc][32 rows]
__device__ unsigned g_cflag[8];                                  // per-chunk producer counters

// ---------------- helpers --------------------------------------------------------
__device__ __forceinline__ uint32_t smem_u32(const void* p) {
    uint32_t a;
    asm("{ .reg .u64 t; cvta.to.shared.u64 t, %1; cvt.u32.u64 %0, t; }" : "=r"(a) : "l"(p));
    return a;
}
__device__ __forceinline__ void mbar_init(uint32_t a, uint32_t cnt) {
    asm volatile("mbarrier.init.shared.b64 [%0], %1;" :: "r"(a), "r"(cnt) : "memory");
}
__device__ __forceinline__ void mbar_expect(uint32_t a, uint32_t tx) {
    asm volatile("mbarrier.arrive.expect_tx.shared.b64 _, [%0], %1;" :: "r"(a), "r"(tx) : "memory");
}
__device__ __forceinline__ void mbar_wait(uint32_t a, uint32_t parity) {
    asm volatile(
        "{\n\t.reg .pred P;\n\t"
        "WL_%=:\n\t"
        "mbarrier.try_wait.parity.acquire.cta.shared::cta.b64 P, [%0], %1, 0x989680;\n\t"
        "@P bra WD_%=;\n\t"
        "bra WL_%=;\n\t"
        "WD_%=:\n\t}"
        :: "r"(a), "r"(parity) : "memory");
}
__device__ __forceinline__ void bulk_g2s(uint32_t dst, const void* src, uint32_t bytes,
                                         uint32_t mbar) {
    asm volatile(
        "cp.async.bulk.shared::cta.global.mbarrier::complete_tx::bytes [%0], [%1], %2, [%3];"
        :: "r"(dst), "l"(src), "r"(bytes), "r"(mbar) : "memory");
}
__device__ __forceinline__ void ldm_x4(uint32_t& r0, uint32_t& r1, uint32_t& r2,
                                       uint32_t& r3, uint32_t addr) {
    asm volatile("ldmatrix.sync.aligned.m8n8.x4.shared.b16 {%0,%1,%2,%3}, [%4];"
                 : "=r"(r0), "=r"(r1), "=r"(r2), "=r"(r3) : "r"(addr));
}
__device__ __forceinline__ void mma_bf16(float* c, uint32_t a0, uint32_t a1,
                                         uint32_t a2, uint32_t a3,
                                         uint32_t b0, uint32_t b1) {
    asm volatile(
        "mma.sync.aligned.m16n8k16.row.col.f32.bf16.bf16.f32 "
        "{%0,%1,%2,%3}, {%4,%5,%6,%7}, {%8,%9}, {%0,%1,%2,%3};"
        : "+f"(c[0]), "+f"(c[1]), "+f"(c[2]), "+f"(c[3])
        : "r"(a0), "r"(a1), "r"(a2), "r"(a3), "r"(b0), "r"(b1));
}
__device__ __forceinline__ ull pack2(float x, float y) {
    ull r; asm("mov.b64 %0, {%1,%2};" : "=l"(r) : "f"(x), "f"(y)); return r;
}
__device__ __forceinline__ void unpack2(ull v, float& x, float& y) {
    asm("mov.b64 {%0,%1}, %2;" : "=f"(x), "=f"(y) : "l"(v));
}
__device__ __forceinline__ void ffma2(ull& d, ull a, ull b) {
    asm("fma.rn.f32x2 %0, %1, %2, %0;" : "+l"(d) : "l"(a), "l"(b));
}
__device__ __forceinline__ float sigm_(float x) {
    return __fdividef(1.0f, 1.0f + __expf(-x));
}
__device__ __forceinline__ float tanh_(float x) {
    return 1.0f - __fdividef(2.0f, __expf(2.0f * x) + 1.0f);
}

// ---------------- init ------------------------------------------------------------
__global__ void init_state(float* __restrict__ out) {
    int i = blockIdx.x * blockDim.x + threadIdx.x;  // 65536 threads
    ((uint32_t*)g_h_img[0])[i] = 0u;   // zero pp=0 h image (256 KB)
    out[i] = 0.0f;
    if (i < 8) g_cflag[i] = 0u;
}

// ---------------- W_hh -> pre-swizzled per-CTA chunk images -------------------------
__global__ __launch_bounds__(256) void w_prep(const float* __restrict__ Whh) {
    int bid = blockIdx.x;            // 4096 = 128 jb x 32 nl
    int jb = bid >> 5;
    int nl = bid & 31;
    int grow = (nl >> 3) * Hdim + jb * 8 + (nl & 7);
    const float* src = Whh + (size_t)grow * Hdim;
#pragma unroll
    for (int q = 0; q < 4; q++) {
        int k = q * 256 + threadIdx.x;
        float w = src[k];
        __nv_bfloat16 hi = __float2bfloat16(w);
        __nv_bfloat16 lo = __float2bfloat16(w - __bfloat162float(hi));
        int kc = k >> 7;
        int kk = k & 127;
        int seg = kk >> 3;
        uint32_t off = (uint32_t)(nl * 256 + ((seg ^ (nl & 7)) << 4) + (kk & 7) * 2);
        *(__nv_bfloat16*)(&g_w_img[jb][0][kc][off]) = hi;
        *(__nv_bfloat16*)(&g_w_img[jb][1][kc][off]) = lo;
    }
}

// ---------------- GEMM1 (fp32x2 SIMT, proven) ---------------------------------------
__global__ __launch_bounds__(256) void gates_x_gemm(
    const float* __restrict__ seq, const float* __restrict__ Wih,
    const float* __restrict__ bih, const float* __restrict__ bhh) {
    __shared__ float As[8][132];
    __shared__ float Bs[8][132];

    const int tid = threadIdx.x;
    const int tx = tid & 15;
    const int ty = tid >> 4;
    const int m0 = blockIdx.y * 128;
    const int n0 = blockIdx.x * 128;

    const int lr = tid >> 1;
    const int lk = (tid & 1) * 4;
    const float* aptr = seq + (size_t)(m0 + lr) * Idim + lk;
    const float* bptr = Wih + (size_t)(n0 + lr) * Idim + lk;

    ull acc[8][4];
#pragma unroll
    for (int i = 0; i < 8; i++)
#pragma unroll
        for (int j = 0; j < 4; j++) acc[i][j] = 0ull;

    for (int k0 = 0; k0 < Idim; k0 += 8) {
        float4 av = *(const float4*)(aptr + k0);
        float4 bv = *(const float4*)(bptr + k0);
        As[lk + 0][lr] = av.x; As[lk + 1][lr] = av.y;
        As[lk + 2][lr] = av.z; As[lk + 3][lr] = av.w;
        Bs[lk + 0][lr] = bv.x; Bs[lk + 1][lr] = bv.y;
        Bs[lk + 2][lr] = bv.z; Bs[lk + 3][lr] = bv.w;
        __syncthreads();
#pragma unroll
        for (int k = 0; k < 8; k++) {
            float4 a0 = *(const float4*)&As[k][ty * 8];
            float4 a1 = *(const float4*)&As[k][ty * 8 + 4];
            ull pb0 = *(const ull*)&Bs[k][tx * 8 + 0];
            ull pb1 = *(const ull*)&Bs[k][tx * 8 + 2];
            ull pb2 = *(const ull*)&Bs[k][tx * 8 + 4];
            ull pb3 = *(const ull*)&Bs[k][tx * 8 + 6];
            float am[8] = {a0.x, a0.y, a0.z, a0.w, a1.x, a1.y, a1.z, a1.w};
#pragma unroll
            for (int i = 0; i < 8; i++) {
                ull pa = pack2(am[i], am[i]);
                ffma2(acc[i][0], pa, pb0);
                ffma2(acc[i][1], pa, pb1);
                ffma2(acc[i][2], pa, pb2);
                ffma2(acc[i][3], pa, pb3);
            }
        }
        __syncthreads();
    }

#pragma unroll
    for (int i = 0; i < 8; i++) {
        int m = m0 + ty * 8 + i;
        int b = m >> 9;        // T = 512
        int t = m & 511;
        float* orow = g_gates_x + (size_t)(t * Bdim + b) * Gdim;
#pragma unroll
        for (int j = 0; j < 4; j++) {
            int n = n0 + tx * 8 + j * 2;
            float x, y; unpack2(acc[i][j], x, y);
            orow[n]     = x + bih[n]     + bhh[n];
            orow[n + 1] = y + bih[n + 1] + bhh[n + 1];
        }
    }
}

// ---------------- persistent HMMA recurrence (per-chunk flags, no global barrier) ---
// 128 CTAs (1/SM) x 256 thr. W resident in smem; h streamed via bulk DMA 2-stage ring.
// Synchronization: chunk kc of step-t input was produced by CTAs [16kc,16kc+16) in
// their step-(t-1) epilogues; consumer polls g_cflag[kc] >= 16*t before the bulk copy.
// No all-to-all barrier; steps pipeline across CTAs.
#define OFF_W 0                          // [plane][kc][8192] = 131072 B
#define OFF_H 131072                     // 2 stages x (Ahi 16384 | Alo 16384)
#define OFF_PRE (OFF_H + 2 * 32768)      // 196608
#define OFF_MBAR (OFF_PRE + 64 * 36 * 4) // 205824 (mb_h0, mb_h1, mb_w)
#define SMEM_BYTES (OFF_MBAR + 64)       // 205888

__global__ __launch_bounds__(256, 1) void lstm_persist(
    const int* __restrict__ lens, float* __restrict__ out) {
    extern __shared__ unsigned char smem[];
    const uint32_t sb = smem_u32(smem);
    float* pre = (float*)(smem + OFF_PRE);        // [64][36]
    const uint32_t mb_h = sb + OFF_MBAR;          // 2 stage mbars, 8B apart
    const uint32_t mb_w = sb + OFF_MBAR + 16;

    const int tid = threadIdx.x;
    const int lane = tid & 31;
    const int w = tid >> 5;
    const int mt = w & 3;
    const int nh = w >> 2;
    const int jb = blockIdx.x;
    const int j0 = jb * 8;

    if (tid == 0) {
        mbar_init(mb_h, 1);
        mbar_init(mb_h + 8, 1);
        mbar_init(mb_w, 1);
    }
    __syncthreads();

    // ---- one-time: W slice (both planes) -> smem via 2 bulk copies
    if (tid == 0) {
        mbar_expect(mb_w, 131072);
        bulk_g2s(sb + OFF_W,         &g_w_img[jb][0][0][0], 65536, mb_w);
        bulk_g2s(sb + OFF_W + 65536, &g_w_img[jb][1][0][0], 65536, mb_w);
    }
    mbar_wait(mb_w, 0);

    // ---- per-lane fragment addressing (proven rounds 10-12)
    const int rowa = mt * 16 + (lane & 7) + ((lane >> 3) & 1) * 8;   // A row (batch)
    const int selA = (lane >> 4) & 1;
    const int xa = rowa & 7;
    const uint32_t a_base = (uint32_t)(rowa * 256);
    const int rowb = nh * 16 + (lane & 7) + ((lane >> 4) & 1) * 8;   // B row (gate col)
    const int selB = (lane >> 3) & 1;
    const int xb = rowb & 7;
    const uint32_t b_base = (uint32_t)(rowb * 256);

    // ---- persistent per-thread state (threads 0-63: b = tid)
    float cst[8];
#pragma unroll
    for (int q = 0; q < 8; q++) cst[q] = 0.0f;
    const int lb = (tid < 64) ? lens[tid] : 0;

    // epilogue h-image addressing; this CTA produces chunk jc
    const int jc = j0 >> 7;
    const int sg = (j0 & 127) >> 3;

    for (int t = 0; t < Tdim; t++) {
        const int pp = t & 1;
        const unsigned tgt = 16u * (unsigned)t;   // chunk-ready threshold for step t

        // poll producer flag for chunk kc, then issue its bulk copies
        auto issue_chunk = [&](int kc) {
            while (*((volatile unsigned*)&g_cflag[kc]) < tgt) { }
            int n = t * 8 + kc;
            int s = n & 1;
            uint32_t dst = sb + OFF_H + s * 32768;
            uint32_t mb = mb_h + s * 8;
            mbar_expect(mb, 32768);
            bulk_g2s(dst,         &g_h_img[pp][0][kc][0], 16384, mb);
            bulk_g2s(dst + 16384, &g_h_img[pp][1][kc][0], 16384, mb);
        };

        if (tid == 0) { issue_chunk(0); issue_chunk(1); }

        // gates_x prefetch (threads 0-63, b = tid) — overlaps chunk-0 copy latency
        float gx[32];
        if (tid < 64) {
            const float* gxb = g_gates_x + ((size_t)t * Bdim + tid) * Gdim + j0;
#pragma unroll
            for (int g = 0; g < 4; g++) {
                float4 v0 = *(const float4*)(gxb + g * Hdim);
                float4 v1 = *(const float4*)(gxb + g * Hdim + 4);
                gx[g * 8 + 0] = v0.x; gx[g * 8 + 1] = v0.y;
                gx[g * 8 + 2] = v0.z; gx[g * 8 + 3] = v0.w;
                gx[g * 8 + 4] = v1.x; gx[g * 8 + 5] = v1.y;
                gx[g * 8 + 6] = v1.z; gx[g * 8 + 7] = v1.w;
            }
        }

        float C0[2][4], C1[2][4], C2[2][4];
#pragma unroll
        for (int nt = 0; nt < 2; nt++)
#pragma unroll
            for (int k = 0; k < 4; k++) { C0[nt][k] = 0.f; C1[nt][k] = 0.f; C2[nt][k] = 0.f; }

        for (int kc = 0; kc < 8; kc++) {
            int n = t * 8 + kc;
            mbar_wait(mb_h + (n & 1) * 8, (n >> 1) & 1);

            uint32_t abase = sb + OFF_H + (n & 1) * 32768 + a_base;
            uint32_t bbase = sb + OFF_W + kc * 8192 + b_base;
#pragma unroll
            for (int ks = 0; ks < 8; ks++) {
                uint32_t aoff = abase + (uint32_t)((((2 * ks + selA) ^ xa)) << 4);
                uint32_t boff = bbase + (uint32_t)((((2 * ks + selB) ^ xb)) << 4);
                uint32_t ah0, ah1, ah2, ah3, al0, al1, al2, al3;
                ldm_x4(ah0, ah1, ah2, ah3, aoff);
                ldm_x4(al0, al1, al2, al3, aoff + 16384);
                uint32_t p0, p1, p2, p3;          // B hi
                ldm_x4(p0, p1, p2, p3, boff);
                uint32_t s0, s1, s2, s3;          // B lo
                ldm_x4(s0, s1, s2, s3, boff + 65536);

                mma_bf16(C0[0], ah0, ah1, ah2, ah3, p0, p1);
                mma_bf16(C0[1], ah0, ah1, ah2, ah3, p2, p3);
                mma_bf16(C1[0], ah0, ah1, ah2, ah3, s0, s1);
                mma_bf16(C1[1], ah0, ah1, ah2, ah3, s2, s3);
                mma_bf16(C2[0], al0, al1, al2, al3, p0, p1);
                mma_bf16(C2[1], al0, al1, al2, al3, p2, p3);
            }
            __syncthreads();                      // reads of stage n&1 retired
            if (tid == 0 && kc + 2 < 8) issue_chunk(kc + 2);
        }

        // merge split terms -> pre[64][36]
        {
            int g = lane >> 2, t2 = (lane & 3) * 2;
            int m = mt * 16 + g;
#pragma unroll
            for (int nt = 0; nt < 2; nt++) {
                float s0 = C0[nt][0] + C1[nt][0] + C2[nt][0];
                float s1 = C0[nt][1] + C1[nt][1] + C2[nt][1];
                float s2 = C0[nt][2] + C1[nt][2] + C2[nt][2];
                float s3 = C0[nt][3] + C1[nt][3] + C2[nt][3];
                int nn = nh * 16 + nt * 8 + t2;
                *(float2*)&pre[m * 36 + nn]       = make_float2(s0, s1);
                *(float2*)&pre[(m + 8) * 36 + nn] = make_float2(s2, s3);
            }
        }
        __syncthreads();

        // pointwise LSTM cell (threads 0-63, b = tid)
        if (tid < 64) {
            int b = tid;
            float hn[8];
            unsigned short hu[8], lu[8];
#pragma unroll
            for (int jj = 0; jj < 8; jj++) {
                float xi = pre[b * 36 + jj]      + gx[jj];
                float xf = pre[b * 36 + 8 + jj]  + gx[8 + jj];
                float xg = pre[b * 36 + 16 + jj] + gx[16 + jj];
                float xo = pre[b * 36 + 24 + jj] + gx[24 + jj];
                float i_ = sigm_(xi), f_ = sigm_(xf), g_ = tanh_(xg), o_ = sigm_(xo);
                float cn = f_ * cst[jj] + i_ * g_;
                cst[jj] = cn;
                float h = o_ * tanh_(cn);
                hn[jj] = h;
                __nv_bfloat16 hh = __float2bfloat16(h);
                __nv_bfloat16 hl = __float2bfloat16(h - __bfloat162float(hh));
                hu[jj] = __bfloat16_as_ushort(hh);
                lu[jj] = __bfloat16_as_ushort(hl);
            }
            uint4 vh, vl;
            vh.x = (uint32_t)hu[0] | ((uint32_t)hu[1] << 16);
            vh.y = (uint32_t)hu[2] | ((uint32_t)hu[3] << 16);
            vh.z = (uint32_t)hu[4] | ((uint32_t)hu[5] << 16);
            vh.w = (uint32_t)hu[6] | ((uint32_t)hu[7] << 16);
            vl.x = (uint32_t)lu[0] | ((uint32_t)lu[1] << 16);
            vl.y = (uint32_t)lu[2] | ((uint32_t)lu[3] << 16);
            vl.z = (uint32_t)lu[4] | ((uint32_t)lu[5] << 16);
            vl.w = (uint32_t)lu[6] | ((uint32_t)lu[7] << 16);

            int pp1 = pp ^ 1;
            uint32_t hoff = (uint32_t)(b * 256 + ((sg ^ (b & 7)) << 4));
            *(uint4*)(&g_h_img[pp1][0][jc][hoff]) = vh;
            *(uint4*)(&g_h_img[pp1][1][jc][hoff]) = vl;

            if (lb > t) {
                float* ob = out + (size_t)b * Hdim + j0;
                *(float4*)(ob)     = make_float4(hn[0], hn[1], hn[2], hn[3]);
                *(float4*)(ob + 4) = make_float4(hn[4], hn[5], hn[6], hn[7]);
            }
            // make generic-proxy h stores visible to async-proxy bulk reads
            asm volatile("fence.proxy.async;" ::: "memory");
            __threadfence();                       // release h-image writes to L2
        }

        // signal: this CTA's slice of chunk jc for step t+1 is ready
        __syncthreads();
        if (tid == 0) {
            atomicAdd(&g_cflag[jc], 1u);
        }
    }
}

// ---------------- launch ------------------------------------------------------------
extern "C" void kernel_launch(void* const* d_in, const int* in_sizes, int n_in,
                              void* d_out, int out_size) {
    const float* seq   = (const float*)d_in[0];
    const int*   lensp = (const int*)d_in[1];
    const float* Wih   = (const float*)d_in[2];
    const float* Whh   = (const float*)d_in[3];
    const float* bih   = (const float*)d_in[4];
    const float* bhh   = (const float*)d_in[5];
    float* out = (float*)d_out;

    cudaFuncSetAttribute(lstm_persist,
                         cudaFuncAttributeMaxDynamicSharedMemorySize, SMEM_BYTES);

    init_state<<<256, 256>>>(out);
    w_prep<<<4096, 256>>>(Whh);

    dim3 g1(Gdim / 128, (Bdim * Tdim) / 128);
    gates_x_gemm<<<g1, 256>>>(seq, Wih, bih, bhh);

    lstm_persist<<<NCTA, 256, SMEM_BYTES>>>(lensp, out);
}

// round 14
// speedup vs baseline: 1.4072x; 1.0200x over previous
#include <cuda_runtime.h>
#include <cuda_bf16.h>
#include <cstdint>

#define Bdim 64
#define Tdim 512
#define Idim 512
#define Hdim 1024
#define Gdim 4096
#define NCTA 128

typedef unsigned long long ull;

// ---------------- device globals (allocation-free scratch) ----------------------
__device__ float g_gates_x[(size_t)Tdim * Bdim * Gdim];          // [t][b][4096]
// pre-swizzled chunk images: row*256B + ((seg ^ (row&7))<<4)
__device__ __align__(16) unsigned char g_h_img[2][2][8][16384];  // [pp][plane][kc][64 rows]
__device__ __align__(16) unsigned char g_w_img[NCTA][2][8][8192]; // [jb][plane][kc][32 rows]
__device__ unsigned g_cflag[8];                                  // per-chunk producer counters

// ---------------- helpers --------------------------------------------------------
__device__ __forceinline__ uint32_t smem_u32(const void* p) {
    uint32_t a;
    asm("{ .reg .u64 t; cvta.to.shared.u64 t, %1; cvt.u32.u64 %0, t; }" : "=r"(a) : "l"(p));
    return a;
}
__device__ __forceinline__ void mbar_init(uint32_t a, uint32_t cnt) {
    asm volatile("mbarrier.init.shared.b64 [%0], %1;" :: "r"(a), "r"(cnt) : "memory");
}
__device__ __forceinline__ void mbar_expect(uint32_t a, uint32_t tx) {
    asm volatile("mbarrier.arrive.expect_tx.shared.b64 _, [%0], %1;" :: "r"(a), "r"(tx) : "memory");
}
__device__ __forceinline__ void mbar_wait(uint32_t a, uint32_t parity) {
    asm volatile(
        "{\n\t.reg .pred P;\n\t"
        "WL_%=:\n\t"
        "mbarrier.try_wait.parity.acquire.cta.shared::cta.b64 P, [%0], %1, 0x989680;\n\t"
        "@P bra WD_%=;\n\t"
        "bra WL_%=;\n\t"
        "WD_%=:\n\t}"
        :: "r"(a), "r"(parity) : "memory");
}
__device__ __forceinline__ void bulk_g2s(uint32_t dst, const void* src, uint32_t bytes,
                                         uint32_t mbar) {
    asm volatile(
        "cp.async.bulk.shared::cta.global.mbarrier::complete_tx::bytes [%0], [%1], %2, [%3];"
        :: "r"(dst), "l"(src), "r"(bytes), "r"(mbar) : "memory");
}
__device__ __forceinline__ void ldm_x4(uint32_t& r0, uint32_t& r1, uint32_t& r2,
                                       uint32_t& r3, uint32_t addr) {
    asm volatile("ldmatrix.sync.aligned.m8n8.x4.shared.b16 {%0,%1,%2,%3}, [%4];"
                 : "=r"(r0), "=r"(r1), "=r"(r2), "=r"(r3) : "r"(addr));
}
__device__ __forceinline__ void mma_bf16(float* c, uint32_t a0, uint32_t a1,
                                         uint32_t a2, uint32_t a3,
                                         uint32_t b0, uint32_t b1) {
    asm volatile(
        "mma.sync.aligned.m16n8k16.row.col.f32.bf16.bf16.f32 "
        "{%0,%1,%2,%3}, {%4,%5,%6,%7}, {%8,%9}, {%0,%1,%2,%3};"
        : "+f"(c[0]), "+f"(c[1]), "+f"(c[2]), "+f"(c[3])
        : "r"(a0), "r"(a1), "r"(a2), "r"(a3), "r"(b0), "r"(b1));
}
__device__ __forceinline__ ull pack2(float x, float y) {
    ull r; asm("mov.b64 %0, {%1,%2};" : "=l"(r) : "f"(x), "f"(y)); return r;
}
__device__ __forceinline__ void unpack2(ull v, float& x, float& y) {
    asm("mov.b64 {%0,%1}, %2;" : "=f"(x), "=f"(y) : "l"(v));
}
__device__ __forceinline__ void ffma2(ull& d, ull a, ull b) {
    asm("fma.rn.f32x2 %0, %1, %2, %0;" : "+l"(d) : "l"(a), "l"(b));
}
__device__ __forceinline__ float sigm_(float x) {
    return __fdividef(1.0f, 1.0f + __expf(-x));
}
__device__ __forceinline__ float tanh_(float x) {
    return 1.0f - __fdividef(2.0f, __expf(2.0f * x) + 1.0f);
}

// ---------------- init ------------------------------------------------------------
__global__ void init_state(float* __restrict__ out) {
    int i = blockIdx.x * blockDim.x + threadIdx.x;  // 65536 threads
    ((uint32_t*)g_h_img[0])[i] = 0u;   // zero pp=0 h image (256 KB)
    out[i] = 0.0f;
    if (i < 8) g_cflag[i] = 0u;
}

// ---------------- W_hh -> pre-swizzled per-CTA chunk images -------------------------
__global__ __launch_bounds__(256) void w_prep(const float* __restrict__ Whh) {
    int bid = blockIdx.x;            // 4096 = 128 jb x 32 nl
    int jb = bid >> 5;
    int nl = bid & 31;
    int grow = (nl >> 3) * Hdim + jb * 8 + (nl & 7);
    const float* src = Whh + (size_t)grow * Hdim;
#pragma unroll
    for (int q = 0; q < 4; q++) {
        int k = q * 256 + threadIdx.x;
        float w = src[k];
        __nv_bfloat16 hi = __float2bfloat16(w);
        __nv_bfloat16 lo = __float2bfloat16(w - __bfloat162float(hi));
        int kc = k >> 7;
        int kk = k & 127;
        int seg = kk >> 3;
        uint32_t off = (uint32_t)(nl * 256 + ((seg ^ (nl & 7)) << 4) + (kk & 7) * 2);
        *(__nv_bfloat16*)(&g_w_img[jb][0][kc][off]) = hi;
        *(__nv_bfloat16*)(&g_w_img[jb][1][kc][off]) = lo;
    }
}

// ---------------- GEMM1 (fp32x2 SIMT, proven) ---------------------------------------
__global__ __launch_bounds__(256) void gates_x_gemm(
    const float* __restrict__ seq, const float* __restrict__ Wih,
    const float* __restrict__ bih, const float* __restrict__ bhh) {
    __shared__ float As[8][132];
    __shared__ float Bs[8][132];

    const int tid = threadIdx.x;
    const int tx = tid & 15;
    const int ty = tid >> 4;
    const int m0 = blockIdx.y * 128;
    const int n0 = blockIdx.x * 128;

    const int lr = tid >> 1;
    const int lk = (tid & 1) * 4;
    const float* aptr = seq + (size_t)(m0 + lr) * Idim + lk;
    const float* bptr = Wih + (size_t)(n0 + lr) * Idim + lk;

    ull acc[8][4];
#pragma unroll
    for (int i = 0; i < 8; i++)
#pragma unroll
        for (int j = 0; j < 4; j++) acc[i][j] = 0ull;

    for (int k0 = 0; k0 < Idim; k0 += 8) {
        float4 av = *(const float4*)(aptr + k0);
        float4 bv = *(const float4*)(bptr + k0);
        As[lk + 0][lr] = av.x; As[lk + 1][lr] = av.y;
        As[lk + 2][lr] = av.z; As[lk + 3][lr] = av.w;
        Bs[lk + 0][lr] = bv.x; Bs[lk + 1][lr] = bv.y;
        Bs[lk + 2][lr] = bv.z; Bs[lk + 3][lr] = bv.w;
        __syncthreads();
#pragma unroll
        for (int k = 0; k < 8; k++) {
            float4 a0 = *(const float4*)&As[k][ty * 8];
            float4 a1 = *(const float4*)&As[k][ty * 8 + 4];
            ull pb0 = *(const ull*)&Bs[k][tx * 8 + 0];
            ull pb1 = *(const ull*)&Bs[k][tx * 8 + 2];
            ull pb2 = *(const ull*)&Bs[k][tx * 8 + 4];
            ull pb3 = *(const ull*)&Bs[k][tx * 8 + 6];
            float am[8] = {a0.x, a0.y, a0.z, a0.w, a1.x, a1.y, a1.z, a1.w};
#pragma unroll
            for (int i = 0; i < 8; i++) {
                ull pa = pack2(am[i], am[i]);
                ffma2(acc[i][0], pa, pb0);
                ffma2(acc[i][1], pa, pb1);
                ffma2(acc[i][2], pa, pb2);
                ffma2(acc[i][3], pa, pb3);
            }
        }
        __syncthreads();
    }

#pragma unroll
    for (int i = 0; i < 8; i++) {
        int m = m0 + ty * 8 + i;
        int b = m >> 9;        // T = 512
        int t = m & 511;
        float* orow = g_gates_x + (size_t)(t * Bdim + b) * Gdim;
#pragma unroll
        for (int j = 0; j < 4; j++) {
            int n = n0 + tx * 8 + j * 2;
            float x, y; unpack2(acc[i][j], x, y);
            orow[n]     = x + bih[n]     + bhh[n];
            orow[n + 1] = y + bih[n + 1] + bhh[n + 1];
        }
    }
}

// ---------------- persistent HMMA recurrence (16 warps, m32n16kq4 tiles) ------------
// 128 CTAs (1/SM) x 512 thr. W resident in smem; h via bulk-DMA 2-stage ring; per-chunk
// producer flags (round-13 skeleton). Warp w: kq=w&3 owns k-slices {2kq,2kq+1} of each
// chunk; nh=(w>>2)&1 (gate cols nh*16..); mw=w>>3 (batches mw*32..+31). Per slice:
// 4 A-LDSM.x4 (m32 hi/lo) + 2 B-LDSM.x4 (n16 hi/lo), 12 MMAs. kq partials merged via
// two pre arrays (write kq<2, accumulate kq>=2).
#define OFF_W 0                          // [plane][kc][8192] = 131072 B
#define OFF_H 131072                     // 2 stages x (Ahi 16384 | Alo 16384)
#define OFF_PRE (OFF_H + 2 * 32768)      // 196608
#define PRE_SZ (64 * 36 * 4)             // 9216
#define OFF_MBAR (OFF_PRE + 2 * PRE_SZ)  // 215040
#define SMEM_BYTES (OFF_MBAR + 64)       // 215104

__global__ __launch_bounds__(512, 1) void lstm_persist(
    const int* __restrict__ lens, float* __restrict__ out) {
    extern __shared__ unsigned char smem[];
    const uint32_t sb = smem_u32(smem);
    float* pre0 = (float*)(smem + OFF_PRE);       // [64][36]
    float* pre1 = (float*)(smem + OFF_PRE + PRE_SZ);
    const uint32_t mb_h = sb + OFF_MBAR;          // 2 stage mbars, 8B apart
    const uint32_t mb_w = sb + OFF_MBAR + 16;

    const int tid = threadIdx.x;
    const int lane = tid & 31;
    const int w = tid >> 5;
    const int kq = w & 3;
    const int nh = (w >> 2) & 1;
    const int mw = w >> 3;
    const int jb = blockIdx.x;
    const int j0 = jb * 8;

    if (tid == 0) {
        mbar_init(mb_h, 1);
        mbar_init(mb_h + 8, 1);
        mbar_init(mb_w, 1);
    }
    __syncthreads();

    // ---- one-time: W slice (both planes) -> smem via 2 bulk copies
    if (tid == 0) {
        mbar_expect(mb_w, 131072);
        bulk_g2s(sb + OFF_W,         &g_w_img[jb][0][0][0], 65536, mb_w);
        bulk_g2s(sb + OFF_W + 65536, &g_w_img[jb][1][0][0], 65536, mb_w);
    }
    mbar_wait(mb_w, 0);

    // ---- per-lane fragment addressing (swizzle proven rounds 10-13)
    const int rowa = mw * 32 + (lane & 7) + ((lane >> 3) & 1) * 8;   // A row (batch), lower m16
    const int selA = (lane >> 4) & 1;
    const int xa = rowa & 7;                    // (rowa+16)&7 == xa, so +4096 reuses swizzle
    const uint32_t a_base = (uint32_t)(rowa * 256);
    const int rowb = nh * 16 + (lane & 7) + ((lane >> 4) & 1) * 8;   // B row (gate col)
    const int selB = (lane >> 3) & 1;
    const int xb = rowb & 7;
    const uint32_t b_base = (uint32_t)(rowb * 256);

    // ---- persistent per-thread state (threads 0-63: b = tid)
    float cst[8];
#pragma unroll
    for (int q = 0; q < 8; q++) cst[q] = 0.0f;
    const int lb = (tid < 64) ? lens[tid] : 0;

    // epilogue h-image addressing; this CTA produces chunk jc
    const int jc = j0 >> 7;
    const int sg = (j0 & 127) >> 3;

    for (int t = 0; t < Tdim; t++) {
        const int pp = t & 1;
        const unsigned tgt = 16u * (unsigned)t;   // chunk-ready threshold for step t

        // poll producer flag for chunk kc, then issue its bulk copies
        auto issue_chunk = [&](int kc) {
            while (*((volatile unsigned*)&g_cflag[kc]) < tgt) { }
            int n = t * 8 + kc;
            int s = n & 1;
            uint32_t dst = sb + OFF_H + s * 32768;
            uint32_t mb = mb_h + s * 8;
            mbar_expect(mb, 32768);
            bulk_g2s(dst,         &g_h_img[pp][0][kc][0], 16384, mb);
            bulk_g2s(dst + 16384, &g_h_img[pp][1][kc][0], 16384, mb);
        };

        if (tid == 0) { issue_chunk(0); issue_chunk(1); }

        // gates_x prefetch (threads 0-63, b = tid) — overlaps chunk-0 copy latency
        float gx[32];
        if (tid < 64) {
            const float* gxb = g_gates_x + ((size_t)t * Bdim + tid) * Gdim + j0;
#pragma unroll
            for (int g = 0; g < 4; g++) {
                float4 v0 = *(const float4*)(gxb + g * Hdim);
                float4 v1 = *(const float4*)(gxb + g * Hdim + 4);
                gx[g * 8 + 0] = v0.x; gx[g * 8 + 1] = v0.y;
                gx[g * 8 + 2] = v0.z; gx[g * 8 + 3] = v0.w;
                gx[g * 8 + 4] = v1.x; gx[g * 8 + 5] = v1.y;
                gx[g * 8 + 6] = v1.z; gx[g * 8 + 7] = v1.w;
            }
        }

        // accumulators: [mt2][nt][4] per split term
        float C0[2][2][4], C1[2][2][4], C2[2][2][4];
#pragma unroll
        for (int i = 0; i < 2; i++)
#pragma unroll
            for (int j = 0; j < 2; j++)
#pragma unroll
                for (int k = 0; k < 4; k++) {
                    C0[i][j][k] = 0.f; C1[i][j][k] = 0.f; C2[i][j][k] = 0.f;
                }

        for (int kc = 0; kc < 8; kc++) {
            int n = t * 8 + kc;
            mbar_wait(mb_h + (n & 1) * 8, (n >> 1) & 1);

            uint32_t abase = sb + OFF_H + (n & 1) * 32768 + a_base;
            uint32_t bbase = sb + OFF_W + kc * 8192 + b_base;
#pragma unroll
            for (int s = 0; s < 2; s++) {
                int ks = kq * 2 + s;
                uint32_t aoff = abase + (uint32_t)((((2 * ks + selA) ^ xa)) << 4);
                uint32_t boff = bbase + (uint32_t)((((2 * ks + selB) ^ xb)) << 4);
                uint32_t ah0, ah1, ah2, ah3, ah4, ah5, ah6, ah7;   // A hi: m16 low, m16 high
                uint32_t al0, al1, al2, al3, al4, al5, al6, al7;   // A lo
                ldm_x4(ah0, ah1, ah2, ah3, aoff);
                ldm_x4(ah4, ah5, ah6, ah7, aoff + 4096);
                ldm_x4(al0, al1, al2, al3, aoff + 16384);
                ldm_x4(al4, al5, al6, al7, aoff + 16384 + 4096);
                uint32_t p0, p1, p2, p3;          // B hi (n16)
                ldm_x4(p0, p1, p2, p3, boff);
                uint32_t q0, q1, q2, q3;          // B lo
                ldm_x4(q0, q1, q2, q3, boff + 65536);

                mma_bf16(C0[0][0], ah0, ah1, ah2, ah3, p0, p1);
                mma_bf16(C0[0][1], ah0, ah1, ah2, ah3, p2, p3);
                mma_bf16(C0[1][0], ah4, ah5, ah6, ah7, p0, p1);
                mma_bf16(C0[1][1], ah4, ah5, ah6, ah7, p2, p3);
                mma_bf16(C1[0][0], ah0, ah1, ah2, ah3, q0, q1);
                mma_bf16(C1[0][1], ah0, ah1, ah2, ah3, q2, q3);
                mma_bf16(C1[1][0], ah4, ah5, ah6, ah7, q0, q1);
                mma_bf16(C1[1][1], ah4, ah5, ah6, ah7, q2, q3);
                mma_bf16(C2[0][0], al0, al1, al2, al3, p0, p1);
                mma_bf16(C2[0][1], al0, al1, al2, al3, p2, p3);
                mma_bf16(C2[1][0], al4, al5, al6, al7, p0, p1);
                mma_bf16(C2[1][1], al4, al5, al6, al7, p2, p3);
            }
            __syncthreads();                      // reads of stage n&1 retired
            if (tid == 0 && kc + 2 < 8) issue_chunk(kc + 2);
        }

        // ---- kq-merge: kq<2 write pre[kq], then kq>=2 accumulate into pre[kq-2]
        {
            int g = lane >> 2, t2 = (lane & 3) * 2;
            float* dst = (kq & 1) ? pre1 : pre0;
            if (kq < 2) {
#pragma unroll
                for (int mt2 = 0; mt2 < 2; mt2++)
#pragma unroll
                    for (int nt = 0; nt < 2; nt++) {
                        float s0 = C0[mt2][nt][0] + C1[mt2][nt][0] + C2[mt2][nt][0];
                        float s1 = C0[mt2][nt][1] + C1[mt2][nt][1] + C2[mt2][nt][1];
                        float s2 = C0[mt2][nt][2] + C1[mt2][nt][2] + C2[mt2][nt][2];
                        float s3 = C0[mt2][nt][3] + C1[mt2][nt][3] + C2[mt2][nt][3];
                        int m = mw * 32 + mt2 * 16 + g;
                        int nn = nh * 16 + nt * 8 + t2;
                        *(float2*)&dst[m * 36 + nn]       = make_float2(s0, s1);
                        *(float2*)&dst[(m + 8) * 36 + nn] = make_float2(s2, s3);
                    }
            }
            __syncthreads();
            if (kq >= 2) {
#pragma unroll
                for (int mt2 = 0; mt2 < 2; mt2++)
#pragma unroll
                    for (int nt = 0; nt < 2; nt++) {
                        float s0 = C0[mt2][nt][0] + C1[mt2][nt][0] + C2[mt2][nt][0];
                        float s1 = C0[mt2][nt][1] + C1[mt2][nt][1] + C2[mt2][nt][1];
                        float s2 = C0[mt2][nt][2] + C1[mt2][nt][2] + C2[mt2][nt][2];
                        float s3 = C0[mt2][nt][3] + C1[mt2][nt][3] + C2[mt2][nt][3];
                        int m = mw * 32 + mt2 * 16 + g;
                        int nn = nh * 16 + nt * 8 + t2;
                        float2 a0 = *(float2*)&dst[m * 36 + nn];
                        float2 a1 = *(float2*)&dst[(m + 8) * 36 + nn];
                        *(float2*)&dst[m * 36 + nn]       = make_float2(a0.x + s0, a0.y + s1);
                        *(float2*)&dst[(m + 8) * 36 + nn] = make_float2(a1.x + s2, a1.y + s3);
                    }
            }
        }
        __syncthreads();

        // pointwise LSTM cell (threads 0-63, b = tid)
        if (tid < 64) {
            int b = tid;
            float hn[8];
            unsigned short hu[8], lu[8];
#pragma unroll
            for (int jj = 0; jj < 8; jj++) {
                float xi = pre0[b * 36 + jj]      + pre1[b * 36 + jj]      + gx[jj];
                float xf = pre0[b * 36 + 8 + jj]  + pre1[b * 36 + 8 + jj]  + gx[8 + jj];
                float xg = pre0[b * 36 + 16 + jj] + pre1[b * 36 + 16 + jj] + gx[16 + jj];
                float xo = pre0[b * 36 + 24 + jj] + pre1[b * 36 + 24 + jj] + gx[24 + jj];
                float i_ = sigm_(xi), f_ = sigm_(xf), g_ = tanh_(xg), o_ = sigm_(xo);
                float cn = f_ * cst[jj] + i_ * g_;
                cst[jj] = cn;
                float h = o_ * tanh_(cn);
                hn[jj] = h;
                __nv_bfloat16 hh = __float2bfloat16(h);
                __nv_bfloat16 hl = __float2bfloat16(h - __bfloat162float(hh));
                hu[jj] = __bfloat16_as_ushort(hh);
                lu[jj] = __bfloat16_as_ushort(hl);
            }
            uint4 vh, vl;
            vh.x = (uint32_t)hu[0] | ((uint32_t)hu[1] << 16);
            vh.y = (uint32_t)hu[2] | ((uint32_t)hu[3] << 16);
            vh.z = (uint32_t)hu[4] | ((uint32_t)hu[5] << 16);
            vh.w = (uint32_t)hu[6] | ((uint32_t)hu[7] << 16);
            vl.x = (uint32_t)lu[0] | ((uint32_t)lu[1] << 16);
            vl.y = (uint32_t)lu[2] | ((uint32_t)lu[3] << 16);
            vl.z = (uint32_t)lu[4] | ((uint32_t)lu[5] << 16);
            vl.w = (uint32_t)lu[6] | ((uint32_t)lu[7] << 16);

            int pp1 = pp ^ 1;
            uint32_t hoff = (uint32_t)(b * 256 + ((sg ^ (b & 7)) << 4));
            *(uint4*)(&g_h_img[pp1][0][jc][hoff]) = vh;
            *(uint4*)(&g_h_img[pp1][1][jc][hoff]) = vl;

            if (lb > t) {
                float* ob = out + (size_t)b * Hdim + j0;
                *(float4*)(ob)     = make_float4(hn[0], hn[1], hn[2], hn[3]);
                *(float4*)(ob + 4) = make_float4(hn[4], hn[5], hn[6], hn[7]);
            }
            // make generic-proxy h stores visible to async-proxy bulk reads
            asm volatile("fence.proxy.async;" ::: "memory");
            __threadfence();                       // release h-image writes to L2
        }

        // signal: this CTA's slice of chunk jc for step t+1 is ready
        __syncthreads();
        if (tid == 0) {
            atomicAdd(&g_cflag[jc], 1u);
        }
    }
}

// ---------------- launch ------------------------------------------------------------
extern "C" void kernel_launch(void* const* d_in, const int* in_sizes, int n_in,
                              void* d_out, int out_size) {
    const float* seq   = (const float*)d_in[0];
    const int*   lensp = (const int*)d_in[1];
    const float* Wih   = (const float*)d_in[2];
    const float* Whh   = (const float*)d_in[3];
    const float* bih   = (const float*)d_in[4];
    const float* bhh   = (const float*)d_in[5];
    float* out = (float*)d_out;

    cudaFuncSetAttribute(lstm_persist,
                         cudaFuncAttributeMaxDynamicSharedMemorySize, SMEM_BYTES);

    init_state<<<256, 256>>>(out);
    w_prep<<<4096, 256>>>(Whh);

    dim3 g1(Gdim / 128, (Bdim * Tdim) / 128);
    gates_x_gemm<<<g1, 256>>>(seq, Wih, bih, bhh);

    lstm_persist<<<NCTA, 512, SMEM_BYTES>>>(lensp, out);
}

// round 15
// speedup vs baseline: 2.0007x; 1.4218x over previous
#include <cuda_runtime.h>
#include <cuda_bf16.h>
#include <cstdint>

#define Bdim 64
#define Tdim 512
#define Idim 512
#define Hdim 1024
#define Gdim 4096
#define NCTA 128

typedef unsigned long long ull;

// ---------------- device globals (allocation-free scratch) ----------------------
__device__ float g_gates_x[(size_t)Tdim * Bdim * Gdim];          // [t][b][4096]
// pre-swizzled chunk images: row*pitch + ((seg ^ (row&7))<<4)
__device__ __align__(16) unsigned char g_h_img[2][2][8][16384];  // [pp][plane][kc][64 rows x 256B]
__device__ __align__(16) unsigned char g_w_img[NCTA][2][8][8192]; // [jb][plane][kc][32 rows x 256B]
__device__ unsigned g_cflag[8];                                  // per-chunk producer counters
// GEMM1 images: 128 rows x 64 k bf16 (pitch 128B) per chunk
__device__ __align__(16) unsigned char g_a_img[2][256][8][16384]; // [plane][mblk][kc]
__device__ __align__(16) unsigned char g_b_img[2][32][8][16384];  // [plane][nblk][kc]

// ---------------- helpers --------------------------------------------------------
__device__ __forceinline__ uint32_t smem_u32(const void* p) {
    uint32_t a;
    asm("{ .reg .u64 t; cvta.to.shared.u64 t, %1; cvt.u32.u64 %0, t; }" : "=r"(a) : "l"(p));
    return a;
}
__device__ __forceinline__ void mbar_init(uint32_t a, uint32_t cnt) {
    asm volatile("mbarrier.init.shared.b64 [%0], %1;" :: "r"(a), "r"(cnt) : "memory");
}
__device__ __forceinline__ void mbar_expect(uint32_t a, uint32_t tx) {
    asm volatile("mbarrier.arrive.expect_tx.shared.b64 _, [%0], %1;" :: "r"(a), "r"(tx) : "memory");
}
__device__ __forceinline__ void mbar_wait(uint32_t a, uint32_t parity) {
    asm volatile(
        "{\n\t.reg .pred P;\n\t"
        "WL_%=:\n\t"
        "mbarrier.try_wait.parity.acquire.cta.shared::cta.b64 P, [%0], %1, 0x989680;\n\t"
        "@P bra WD_%=;\n\t"
        "bra WL_%=;\n\t"
        "WD_%=:\n\t}"
        :: "r"(a), "r"(parity) : "memory");
}
__device__ __forceinline__ void bulk_g2s(uint32_t dst, const void* src, uint32_t bytes,
                                         uint32_t mbar) {
    asm volatile(
        "cp.async.bulk.shared::cta.global.mbarrier::complete_tx::bytes [%0], [%1], %2, [%3];"
        :: "r"(dst), "l"(src), "r"(bytes), "r"(mbar) : "memory");
}
__device__ __forceinline__ void ldm_x4(uint32_t& r0, uint32_t& r1, uint32_t& r2,
                                       uint32_t& r3, uint32_t addr) {
    asm volatile("ldmatrix.sync.aligned.m8n8.x4.shared.b16 {%0,%1,%2,%3}, [%4];"
                 : "=r"(r0), "=r"(r1), "=r"(r2), "=r"(r3) : "r"(addr));
}
__device__ __forceinline__ void mma_bf16(float* c, uint32_t a0, uint32_t a1,
                                         uint32_t a2, uint32_t a3,
                                         uint32_t b0, uint32_t b1) {
    asm volatile(
        "mma.sync.aligned.m16n8k16.row.col.f32.bf16.bf16.f32 "
        "{%0,%1,%2,%3}, {%4,%5,%6,%7}, {%8,%9}, {%0,%1,%2,%3};"
        : "+f"(c[0]), "+f"(c[1]), "+f"(c[2]), "+f"(c[3])
        : "r"(a0), "r"(a1), "r"(a2), "r"(a3), "r"(b0), "r"(b1));
}
__device__ __forceinline__ float sigm_(float x) {
    return __fdividef(1.0f, 1.0f + __expf(-x));
}
__device__ __forceinline__ float tanh_(float x) {
    return 1.0f - __fdividef(2.0f, __expf(2.0f * x) + 1.0f);
}

// ---------------- init ------------------------------------------------------------
__global__ void init_state(float* __restrict__ out) {
    int i = blockIdx.x * blockDim.x + threadIdx.x;  // 65536 threads
    ((uint32_t*)g_h_img[0])[i] = 0u;   // zero pp=0 h image (256 KB)
    out[i] = 0.0f;
    if (i < 8) g_cflag[i] = 0u;
}

// ---------------- W_hh -> pre-swizzled per-CTA chunk images -------------------------
__global__ __launch_bounds__(256) void w_prep(const float* __restrict__ Whh) {
    int bid = blockIdx.x;            // 4096 = 128 jb x 32 nl
    int jb = bid >> 5;
    int nl = bid & 31;
    int grow = (nl >> 3) * Hdim + jb * 8 + (nl & 7);
    const float* src = Whh + (size_t)grow * Hdim;
#pragma unroll
    for (int q = 0; q < 4; q++) {
        int k = q * 256 + threadIdx.x;
        float w = src[k];
        __nv_bfloat16 hi = __float2bfloat16(w);
        __nv_bfloat16 lo = __float2bfloat16(w - __bfloat162float(hi));
        int kc = k >> 7;
        int kk = k & 127;
        int seg = kk >> 3;
        uint32_t off = (uint32_t)(nl * 256 + ((seg ^ (nl & 7)) << 4) + (kk & 7) * 2);
        *(__nv_bfloat16*)(&g_w_img[jb][0][kc][off]) = hi;
        *(__nv_bfloat16*)(&g_w_img[jb][1][kc][off]) = lo;
    }
}

// ---------------- seq / W_ih -> pre-swizzled GEMM1 images ---------------------------
// image chunk: 128 rows x 64 k bf16, pitch 128B, off = row*128 + ((seg^(row&7))<<4) + (kk&7)*2
__global__ __launch_bounds__(256) void a_prep(const float* __restrict__ seq) {
    int m = blockIdx.x;              // 0..32767 (= b*512 + t)
    int mblk = m >> 7;
    int row = m & 127;
    const float* src = seq + (size_t)m * Idim;
#pragma unroll
    for (int q = 0; q < 2; q++) {
        int k = q * 256 + threadIdx.x;
        float v = src[k];
        __nv_bfloat16 hi = __float2bfloat16(v);
        __nv_bfloat16 lo = __float2bfloat16(v - __bfloat162float(hi));
        int kc = k >> 6;
        int kk = k & 63;
        int seg = kk >> 3;
        uint32_t off = (uint32_t)(row * 128 + ((seg ^ (row & 7)) << 4) + (kk & 7) * 2);
        *(__nv_bfloat16*)(&g_a_img[0][mblk][kc][off]) = hi;
        *(__nv_bfloat16*)(&g_a_img[1][mblk][kc][off]) = lo;
    }
}
__global__ __launch_bounds__(256) void b_prep(const float* __restrict__ Wih) {
    int n = blockIdx.x;              // 0..4095
    int nblk = n >> 7;
    int row = n & 127;
    const float* src = Wih + (size_t)n * Idim;
#pragma unroll
    for (int q = 0; q < 2; q++) {
        int k = q * 256 + threadIdx.x;
        float v = src[k];
        __nv_bfloat16 hi = __float2bfloat16(v);
        __nv_bfloat16 lo = __float2bfloat16(v - __bfloat162float(hi));
        int kc = k >> 6;
        int kk = k & 63;
        int seg = kk >> 3;
        uint32_t off = (uint32_t)(row * 128 + ((seg ^ (row & 7)) << 4) + (kk & 7) * 2);
        *(__nv_bfloat16*)(&g_b_img[0][nblk][kc][off]) = hi;
        *(__nv_bfloat16*)(&g_b_img[1][nblk][kc][off]) = lo;
    }
}

// ---------------- GEMM1: HMMA split-bf16, bulk-DMA 3-stage pipeline -----------------
// grid (32 n-blk, 256 m-blk) x 256 thr (8 warps). CTA computes 128x128; K=512 in 8
// chunks of 64. Warp w: mt=w&3 (rows mt*32..+31), nh=w>>2 (cols nh*64..+63).
// Per k16 slice: A 4 ldm.x4 (m32 hi/lo) + B 8 ldm.x4 (n64 hi/lo), 48 MMAs (3 terms,
// single accumulator set). Epilogue adds bias, writes gates_x[t][b][n] (round-4 layout).
#define G1_STG 65536                    // Ah 0 | Al 16384 | Bh 32768 | Bl 49152
#define G1_MBAR (3 * G1_STG)            // 196608
#define G1_SMEM (G1_MBAR + 64)

__global__ __launch_bounds__(256) void gemm1_mma(
    const float* __restrict__ bih, const float* __restrict__ bhh) {
    extern __shared__ unsigned char smem[];
    const uint32_t sb = smem_u32(smem);
    const uint32_t mb0 = sb + G1_MBAR;

    const int tid = threadIdx.x;
    const int lane = tid & 31;
    const int w = tid >> 5;
    const int mt = w & 3;
    const int nh = w >> 2;
    const int nblk = blockIdx.x;
    const int mblk = blockIdx.y;

    if (tid == 0) {
#pragma unroll
        for (int s = 0; s < 3; s++) mbar_init(mb0 + s * 8, 1);
    }
    __syncthreads();

    auto issue_chunk = [&](int kc) {
        int s = kc % 3;
        uint32_t dst = sb + s * G1_STG;
        uint32_t mb = mb0 + s * 8;
        mbar_expect(mb, 65536);
        bulk_g2s(dst,         &g_a_img[0][mblk][kc][0], 16384, mb);
        bulk_g2s(dst + 16384, &g_a_img[1][mblk][kc][0], 16384, mb);
        bulk_g2s(dst + 32768, &g_b_img[0][nblk][kc][0], 16384, mb);
        bulk_g2s(dst + 49152, &g_b_img[1][nblk][kc][0], 16384, mb);
    };
    if (tid == 0) { issue_chunk(0); issue_chunk(1); issue_chunk(2); }

    // fragment addressing (pitch 128B, 8 segs; swizzle pattern proven in rounds 10-14)
    const int rowa = mt * 32 + (lane & 7) + ((lane >> 3) & 1) * 8;   // lower m16
    const int selA = (lane >> 4) & 1;
    const int xa = rowa & 7;                 // (rowa+16)&7 == xa
    const uint32_t a_base = (uint32_t)(rowa * 128);
    const int rowb = nh * 64 + (lane & 7) + ((lane >> 4) & 1) * 8;   // first n16 tile
    const int selB = (lane >> 3) & 1;
    const int xb = rowb & 7;                 // +16-row tiles keep same &7
    const uint32_t b_base = (uint32_t)(32768 + rowb * 128);

    float C[2][8][4];                         // [m16][n8][frag]
#pragma unroll
    for (int i = 0; i < 2; i++)
#pragma unroll
        for (int j = 0; j < 8; j++)
#pragma unroll
            for (int k = 0; k < 4; k++) C[i][j][k] = 0.f;

    for (int kc = 0; kc < 8; kc++) {
        mbar_wait(mb0 + (kc % 3) * 8, (kc / 3) & 1);
        uint32_t base = sb + (kc % 3) * G1_STG;
#pragma unroll
        for (int ks = 0; ks < 4; ks++) {
            uint32_t aoff = base + a_base + (uint32_t)((((2 * ks + selA) ^ xa)) << 4);
            uint32_t boff = base + b_base + (uint32_t)((((2 * ks + selB) ^ xb)) << 4);
            uint32_t ah0, ah1, ah2, ah3, ah4, ah5, ah6, ah7;
            uint32_t al0, al1, al2, al3, al4, al5, al6, al7;
            ldm_x4(ah0, ah1, ah2, ah3, aoff);
            ldm_x4(ah4, ah5, ah6, ah7, aoff + 2048);
            ldm_x4(al0, al1, al2, al3, aoff + 16384);
            ldm_x4(al4, al5, al6, al7, aoff + 16384 + 2048);
#pragma unroll
            for (int nt = 0; nt < 4; nt++) {
                uint32_t p0, p1, p2, p3, q0, q1, q2, q3;
                ldm_x4(p0, p1, p2, p3, boff + nt * 2048);          // B hi (n16)
                ldm_x4(q0, q1, q2, q3, boff + 16384 + nt * 2048);  // B lo
                mma_bf16(C[0][nt * 2 + 0], ah0, ah1, ah2, ah3, p0, p1);
                mma_bf16(C[0][nt * 2 + 1], ah0, ah1, ah2, ah3, p2, p3);
                mma_bf16(C[1][nt * 2 + 0], ah4, ah5, ah6, ah7, p0, p1);
                mma_bf16(C[1][nt * 2 + 1], ah4, ah5, ah6, ah7, p2, p3);
                mma_bf16(C[0][nt * 2 + 0], ah0, ah1, ah2, ah3, q0, q1);
                mma_bf16(C[0][nt * 2 + 1], ah0, ah1, ah2, ah3, q2, q3);
                mma_bf16(C[1][nt * 2 + 0], ah4, ah5, ah6, ah7, q0, q1);
                mma_bf16(C[1][nt * 2 + 1], ah4, ah5, ah6, ah7, q2, q3);
                mma_bf16(C[0][nt * 2 + 0], al0, al1, al2, al3, p0, p1);
                mma_bf16(C[0][nt * 2 + 1], al0, al1, al2, al3, p2, p3);
                mma_bf16(C[1][nt * 2 + 0], al4, al5, al6, al7, p0, p1);
                mma_bf16(C[1][nt * 2 + 1], al4, al5, al6, al7, p2, p3);
            }
        }
        __syncthreads();                      // all warps done with stage kc%3
        if (tid == 0 && kc + 3 < 8) issue_chunk(kc + 3);
    }

    // epilogue: add bias, write gates_x in [t][b][n] layout (round-4 proven writes)
    {
        int g = lane >> 2, t2 = (lane & 3) * 2;
#pragma unroll
        for (int mi = 0; mi < 2; mi++) {
            int mrow = mblk * 128 + mt * 32 + mi * 16 + g;
            int b0 = mrow >> 9, t0 = mrow & 511;
            int mrow8 = mrow + 8;
            int b1 = mrow8 >> 9, t1 = mrow8 & 511;
            float* o0 = g_gates_x + ((size_t)t0 * Bdim + b0) * Gdim;
            float* o1 = g_gates_x + ((size_t)t1 * Bdim + b1) * Gdim;
#pragma unroll
            for (int f = 0; f < 8; f++) {
                int n = nblk * 128 + nh * 64 + f * 8 + t2;
                float bs0 = bih[n] + bhh[n];
                float bs1 = bih[n + 1] + bhh[n + 1];
                o0[n]     = C[mi][f][0] + bs0;
                o0[n + 1] = C[mi][f][1] + bs1;
                o1[n]     = C[mi][f][2] + bs0;
                o1[n + 1] = C[mi][f][3] + bs1;
            }
        }
    }
}

// ---------------- persistent HMMA recurrence (round-14, best) -----------------------
#define OFF_W 0                          // [plane][kc][8192] = 131072 B
#define OFF_H 131072                     // 2 stages x (Ahi 16384 | Alo 16384)
#define OFF_PRE (OFF_H + 2 * 32768)      // 196608
#define PRE_SZ (64 * 36 * 4)             // 9216
#define OFF_MBAR (OFF_PRE + 2 * PRE_SZ)  // 215040
#define SMEM_BYTES (OFF_MBAR + 64)       // 215104

__global__ __launch_bounds__(512, 1) void lstm_persist(
    const int* __restrict__ lens, float* __restrict__ out) {
    extern __shared__ unsigned char smem[];
    const uint32_t sb = smem_u32(smem);
    float* pre0 = (float*)(smem + OFF_PRE);       // [64][36]
    float* pre1 = (float*)(smem + OFF_PRE + PRE_SZ);
    const uint32_t mb_h = sb + OFF_MBAR;
    const uint32_t mb_w = sb + OFF_MBAR + 16;

    const int tid = threadIdx.x;
    const int lane = tid & 31;
    const int w = tid >> 5;
    const int kq = w & 3;
    const int nh = (w >> 2) & 1;
    const int mw = w >> 3;
    const int jb = blockIdx.x;
    const int j0 = jb * 8;

    if (tid == 0) {
        mbar_init(mb_h, 1);
        mbar_init(mb_h + 8, 1);
        mbar_init(mb_w, 1);
    }
    __syncthreads();

    if (tid == 0) {
        mbar_expect(mb_w, 131072);
        bulk_g2s(sb + OFF_W,         &g_w_img[jb][0][0][0], 65536, mb_w);
        bulk_g2s(sb + OFF_W + 65536, &g_w_img[jb][1][0][0], 65536, mb_w);
    }
    mbar_wait(mb_w, 0);

    const int rowa = mw * 32 + (lane & 7) + ((lane >> 3) & 1) * 8;
    const int selA = (lane >> 4) & 1;
    const int xa = rowa & 7;
    const uint32_t a_base = (uint32_t)(rowa * 256);
    const int rowb = nh * 16 + (lane & 7) + ((lane >> 4) & 1) * 8;
    const int selB = (lane >> 3) & 1;
    const int xb = rowb & 7;
    const uint32_t b_base = (uint32_t)(rowb * 256);

    float cst[8];
#pragma unroll
    for (int q = 0; q < 8; q++) cst[q] = 0.0f;
    const int lb = (tid < 64) ? lens[tid] : 0;

    const int jc = j0 >> 7;
    const int sg = (j0 & 127) >> 3;

    for (int t = 0; t < Tdim; t++) {
        const int pp = t & 1;
        const unsigned tgt = 16u * (unsigned)t;

        auto issue_chunk = [&](int kc) {
            while (*((volatile unsigned*)&g_cflag[kc]) < tgt) { }
            int n = t * 8 + kc;
            int s = n & 1;
            uint32_t dst = sb + OFF_H + s * 32768;
            uint32_t mb = mb_h + s * 8;
            mbar_expect(mb, 32768);
            bulk_g2s(dst,         &g_h_img[pp][0][kc][0], 16384, mb);
            bulk_g2s(dst + 16384, &g_h_img[pp][1][kc][0], 16384, mb);
        };

        if (tid == 0) { issue_chunk(0); issue_chunk(1); }

        float gx[32];
        if (tid < 64) {
            const float* gxb = g_gates_x + ((size_t)t * Bdim + tid) * Gdim + j0;
#pragma unroll
            for (int g = 0; g < 4; g++) {
                float4 v0 = *(const float4*)(gxb + g * Hdim);
                float4 v1 = *(const float4*)(gxb + g * Hdim + 4);
                gx[g * 8 + 0] = v0.x; gx[g * 8 + 1] = v0.y;
                gx[g * 8 + 2] = v0.z; gx[g * 8 + 3] = v0.w;
                gx[g * 8 + 4] = v1.x; gx[g * 8 + 5] = v1.y;
                gx[g * 8 + 6] = v1.z; gx[g * 8 + 7] = v1.w;
            }
        }

        float C0[2][2][4], C1[2][2][4], C2[2][2][4];
#pragma unroll
        for (int i = 0; i < 2; i++)
#pragma unroll
            for (int j = 0; j < 2; j++)
#pragma unroll
                for (int k = 0; k < 4; k++) {
                    C0[i][j][k] = 0.f; C1[i][j][k] = 0.f; C2[i][j][k] = 0.f;
                }

        for (int kc = 0; kc < 8; kc++) {
            int n = t * 8 + kc;
            mbar_wait(mb_h + (n & 1) * 8, (n >> 1) & 1);

            uint32_t abase = sb + OFF_H + (n & 1) * 32768 + a_base;
            uint32_t bbase = sb + OFF_W + kc * 8192 + b_base;
#pragma unroll
            for (int s = 0; s < 2; s++) {
                int ks = kq * 2 + s;
                uint32_t aoff = abase + (uint32_t)((((2 * ks + selA) ^ xa)) << 4);
                uint32_t boff = bbase + (uint32_t)((((2 * ks + selB) ^ xb)) << 4);
                uint32_t ah0, ah1, ah2, ah3, ah4, ah5, ah6, ah7;
                uint32_t al0, al1, al2, al3, al4, al5, al6, al7;
                ldm_x4(ah0, ah1, ah2, ah3, aoff);
                ldm_x4(ah4, ah5, ah6, ah7, aoff + 4096);
                ldm_x4(al0, al1, al2, al3, aoff + 16384);
                ldm_x4(al4, al5, al6, al7, aoff + 16384 + 4096);
                uint32_t p0, p1, p2, p3;
                ldm_x4(p0, p1, p2, p3, boff);
                uint32_t q0, q1, q2, q3;
                ldm_x4(q0, q1, q2, q3, boff + 65536);

                mma_bf16(C0[0][0], ah0, ah1, ah2, ah3, p0, p1);
                mma_bf16(C0[0][1], ah0, ah1, ah2, ah3, p2, p3);
                mma_bf16(C0[1][0], ah4, ah5, ah6, ah7, p0, p1);
                mma_bf16(C0[1][1], ah4, ah5, ah6, ah7, p2, p3);
                mma_bf16(C1[0][0], ah0, ah1, ah2, ah3, q0, q1);
                mma_bf16(C1[0][1], ah0, ah1, ah2, ah3, q2, q3);
                mma_bf16(C1[1][0], ah4, ah5, ah6, ah7, q0, q1);
                mma_bf16(C1[1][1], ah4, ah5, ah6, ah7, q2, q3);
                mma_bf16(C2[0][0], al0, al1, al2, al3, p0, p1);
                mma_bf16(C2[0][1], al0, al1, al2, al3, p2, p3);
                mma_bf16(C2[1][0], al4, al5, al6, al7, p0, p1);
                mma_bf16(C2[1][1], al4, al5, al6, al7, p2, p3);
            }
            __syncthreads();
            if (tid == 0 && kc + 2 < 8) issue_chunk(kc + 2);
        }

        {
            int g = lane >> 2, t2 = (lane & 3) * 2;
            float* dst = (kq & 1) ? pre1 : pre0;
            if (kq < 2) {
#pragma unroll
                for (int mt2 = 0; mt2 < 2; mt2++)
#pragma unroll
                    for (int nt = 0; nt < 2; nt++) {
                        float s0 = C0[mt2][nt][0] + C1[mt2][nt][0] + C2[mt2][nt][0];
                        float s1 = C0[mt2][nt][1] + C1[mt2][nt][1] + C2[mt2][nt][1];
                        float s2 = C0[mt2][nt][2] + C1[mt2][nt][2] + C2[mt2][nt][2];
                        float s3 = C0[mt2][nt][3] + C1[mt2][nt][3] + C2[mt2][nt][3];
                        int m = mw * 32 + mt2 * 16 + g;
                        int nn = nh * 16 + nt * 8 + t2;
                        *(float2*)&dst[m * 36 + nn]       = make_float2(s0, s1);
                        *(float2*)&dst[(m + 8) * 36 + nn] = make_float2(s2, s3);
                    }
            }
            __syncthreads();
            if (kq >= 2) {
#pragma unroll
                for (int mt2 = 0; mt2 < 2; mt2++)
#pragma unroll
                    for (int nt = 0; nt < 2; nt++) {
                        float s0 = C0[mt2][nt][0] + C1[mt2][nt][0] + C2[mt2][nt][0];
                        float s1 = C0[mt2][nt][1] + C1[mt2][nt][1] + C2[mt2][nt][1];
                        float s2 = C0[mt2][nt][2] + C1[mt2][nt][2] + C2[mt2][nt][2];
                        float s3 = C0[mt2][nt][3] + C1[mt2][nt][3] + C2[mt2][nt][3];
                        int m = mw * 32 + mt2 * 16 + g;
                        int nn = nh * 16 + nt * 8 + t2;
                        float2 a0 = *(float2*)&dst[m * 36 + nn];
                        float2 a1 = *(float2*)&dst[(m + 8) * 36 + nn];
                        *(float2*)&dst[m * 36 + nn]       = make_float2(a0.x + s0, a0.y + s1);
                        *(float2*)&dst[(m + 8) * 36 + nn] = make_float2(a1.x + s2, a1.y + s3);
                    }
            }
        }
        __syncthreads();

        if (tid < 64) {
            int b = tid;
            float hn[8];
            unsigned short hu[8], lu[8];
#pragma unroll
            for (int jj = 0; jj < 8; jj++) {
                float xi = pre0[b * 36 + jj]      + pre1[b * 36 + jj]      + gx[jj];
                float xf = pre0[b * 36 + 8 + jj]  + pre1[b * 36 + 8 + jj]  + gx[8 + jj];
                float xg = pre0[b * 36 + 16 + jj] + pre1[b * 36 + 16 + jj] + gx[16 + jj];
                float xo = pre0[b * 36 + 24 + jj] + pre1[b * 36 + 24 + jj] + gx[24 + jj];
                float i_ = sigm_(xi), f_ = sigm_(xf), g_ = tanh_(xg), o_ = sigm_(xo);
                float cn = f_ * cst[jj] + i_ * g_;
                cst[jj] = cn;
                float h = o_ * tanh_(cn);
                hn[jj] = h;
                __nv_bfloat16 hh = __float2bfloat16(h);
                __nv_bfloat16 hl = __float2bfloat16(h - __bfloat162float(hh));
                hu[jj] = __bfloat16_as_ushort(hh);
                lu[jj] = __bfloat16_as_ushort(hl);
            }
            uint4 vh, vl;
            vh.x = (uint32_t)hu[0] | ((uint32_t)hu[1] << 16);
            vh.y = (uint32_t)hu[2] | ((uint32_t)hu[3] << 16);
            vh.z = (uint32_t)hu[4] | ((uint32_t)hu[5] << 16);
            vh.w = (uint32_t)hu[6] | ((uint32_t)hu[7] << 16);
            vl.x = (uint32_t)lu[0] | ((uint32_t)lu[1] << 16);
            vl.y = (uint32_t)lu[2] | ((uint32_t)lu[3] << 16);
            vl.z = (uint32_t)lu[4] | ((uint32_t)lu[5] << 16);
            vl.w = (uint32_t)lu[6] | ((uint32_t)lu[7] << 16);

            int pp1 = pp ^ 1;
            uint32_t hoff = (uint32_t)(b * 256 + ((sg ^ (b & 7)) << 4));
            *(uint4*)(&g_h_img[pp1][0][jc][hoff]) = vh;
            *(uint4*)(&g_h_img[pp1][1][jc][hoff]) = vl;

            if (lb > t) {
                float* ob = out + (size_t)b * Hdim + j0;
                *(float4*)(ob)     = make_float4(hn[0], hn[1], hn[2], hn[3]);
                *(float4*)(ob + 4) = make_float4(hn[4], hn[5], hn[6], hn[7]);
            }
            asm volatile("fence.proxy.async;" ::: "memory");
            __threadfence();
        }

        __syncthreads();
        if (tid == 0) {
            atomicAdd(&g_cflag[jc], 1u);
        }
    }
}

// ---------------- launch ------------------------------------------------------------
extern "C" void kernel_launch(void* const* d_in, const int* in_sizes, int n_in,
                              void* d_out, int out_size) {
    const float* seq   = (const float*)d_in[0];
    const int*   lensp = (const int*)d_in[1];
    const float* Wih   = (const float*)d_in[2];
    const float* Whh   = (const float*)d_in[3];
    const float* bih   = (const float*)d_in[4];
    const float* bhh   = (const float*)d_in[5];
    float* out = (float*)d_out;

    cudaFuncSetAttribute(lstm_persist,
                         cudaFuncAttributeMaxDynamicSharedMemorySize, SMEM_BYTES);
    cudaFuncSetAttribute(gemm1_mma,
                         cudaFuncAttributeMaxDynamicSharedMemorySize, G1_SMEM);

    init_state<<<256, 256>>>(out);
    w_prep<<<4096, 256>>>(Whh);
    a_prep<<<32768, 256>>>(seq);
    b_prep<<<4096, 256>>>(Wih);

    dim3 g1(Gdim / 128, (Bdim * Tdim) / 128);
    gemm1_mma<<<g1, 256, G1_SMEM>>>(bih, bhh);

    lstm_persist<<<NCTA, 512, SMEM_BYTES>>>(lensp, out);
}

// round 16
// speedup vs baseline: 2.3806x; 1.1899x over previous
#include <cuda_runtime.h>
#include <cuda_bf16.h>
#include <cuda_fp16.h>
#include <cstdint>

#define Bdim 64
#define Tdim 512
#define Idim 512
#define Hdim 1024
#define Gdim 4096
#define NCTA 128

typedef unsigned long long ull;

// ---------------- device globals (allocation-free scratch) ----------------------
__device__ float g_gates_x[(size_t)Tdim * Bdim * Gdim];          // [t][b][4096]
// pre-swizzled chunk images: row*pitch + ((seg ^ (row&7))<<4)
__device__ __align__(16) unsigned char g_h_img[2][8][16384];     // fp16 h [pp][kc][64 rows x 256B]
__device__ __align__(16) unsigned char g_w_img[NCTA][2][8][8192]; // fp16 W hi / lo*2048
__device__ unsigned g_cflag[8];                                  // per-chunk producer counters
// GEMM1 images: 128 rows x 64 k bf16 (pitch 128B) per chunk
__device__ __align__(16) unsigned char g_a_img[2][256][8][16384]; // [plane][mblk][kc]
__device__ __align__(16) unsigned char g_b_img[2][32][8][16384];  // [plane][nblk][kc]

// ---------------- helpers --------------------------------------------------------
__device__ __forceinline__ uint32_t smem_u32(const void* p) {
    uint32_t a;
    asm("{ .reg .u64 t; cvta.to.shared.u64 t, %1; cvt.u32.u64 %0, t; }" : "=r"(a) : "l"(p));
    return a;
}
__device__ __forceinline__ void mbar_init(uint32_t a, uint32_t cnt) {
    asm volatile("mbarrier.init.shared.b64 [%0], %1;" :: "r"(a), "r"(cnt) : "memory");
}
__device__ __forceinline__ void mbar_expect(uint32_t a, uint32_t tx) {
    asm volatile("mbarrier.arrive.expect_tx.shared.b64 _, [%0], %1;" :: "r"(a), "r"(tx) : "memory");
}
__device__ __forceinline__ void mbar_wait(uint32_t a, uint32_t parity) {
    asm volatile(
        "{\n\t.reg .pred P;\n\t"
        "WL_%=:\n\t"
        "mbarrier.try_wait.parity.acquire.cta.shared::cta.b64 P, [%0], %1, 0x989680;\n\t"
        "@P bra WD_%=;\n\t"
        "bra WL_%=;\n\t"
        "WD_%=:\n\t}"
        :: "r"(a), "r"(parity) : "memory");
}
__device__ __forceinline__ void bulk_g2s(uint32_t dst, const void* src, uint32_t bytes,
                                         uint32_t mbar) {
    asm volatile(
        "cp.async.bulk.shared::cta.global.mbarrier::complete_tx::bytes [%0], [%1], %2, [%3];"
        :: "r"(dst), "l"(src), "r"(bytes), "r"(mbar) : "memory");
}
__device__ __forceinline__ void ldm_x4(uint32_t& r0, uint32_t& r1, uint32_t& r2,
                                       uint32_t& r3, uint32_t addr) {
    asm volatile("ldmatrix.sync.aligned.m8n8.x4.shared.b16 {%0,%1,%2,%3}, [%4];"
                 : "=r"(r0), "=r"(r1), "=r"(r2), "=r"(r3) : "r"(addr));
}
__device__ __forceinline__ void mma_bf16(float* c, uint32_t a0, uint32_t a1,
                                         uint32_t a2, uint32_t a3,
                                         uint32_t b0, uint32_t b1) {
    asm volatile(
        "mma.sync.aligned.m16n8k16.row.col.f32.bf16.bf16.f32 "
        "{%0,%1,%2,%3}, {%4,%5,%6,%7}, {%8,%9}, {%0,%1,%2,%3};"
        : "+f"(c[0]), "+f"(c[1]), "+f"(c[2]), "+f"(c[3])
        : "r"(a0), "r"(a1), "r"(a2), "r"(a3), "r"(b0), "r"(b1));
}
__device__ __forceinline__ void mma_f16(float* c, uint32_t a0, uint32_t a1,
                                        uint32_t a2, uint32_t a3,
                                        uint32_t b0, uint32_t b1) {
    asm volatile(
        "mma.sync.aligned.m16n8k16.row.col.f32.f16.f16.f32 "
        "{%0,%1,%2,%3}, {%4,%5,%6,%7}, {%8,%9}, {%0,%1,%2,%3};"
        : "+f"(c[0]), "+f"(c[1]), "+f"(c[2]), "+f"(c[3])
        : "r"(a0), "r"(a1), "r"(a2), "r"(a3), "r"(b0), "r"(b1));
}
__device__ __forceinline__ float sigm_(float x) {
    return __fdividef(1.0f, 1.0f + __expf(-x));
}
__device__ __forceinline__ float tanh_(float x) {
    return 1.0f - __fdividef(2.0f, __expf(2.0f * x) + 1.0f);
}

// ---------------- init ------------------------------------------------------------
__global__ void init_state(float* __restrict__ out) {
    int i = blockIdx.x * blockDim.x + threadIdx.x;  // 65536 threads
    if (i < 32768) ((uint32_t*)g_h_img[0])[i] = 0u;  // zero pp=0 h image (128 KB)
    out[i] = 0.0f;
    if (i < 8) g_cflag[i] = 0u;
}

// ---------------- W_hh -> pre-swizzled fp16 hi / lo*2048 chunk images ---------------
__global__ __launch_bounds__(256) void w_prep(const float* __restrict__ Whh) {
    int bid = blockIdx.x;            // 4096 = 128 jb x 32 nl
    int jb = bid >> 5;
    int nl = bid & 31;
    int grow = (nl >> 3) * Hdim + jb * 8 + (nl & 7);
    const float* src = Whh + (size_t)grow * Hdim;
#pragma unroll
    for (int q = 0; q < 4; q++) {
        int k = q * 256 + threadIdx.x;
        float w = src[k];
        __half hi = __float2half(w);
        __half lo = __float2half((w - __half2float(hi)) * 2048.0f);
        int kc = k >> 7;
        int kk = k & 127;
        int seg = kk >> 3;
        uint32_t off = (uint32_t)(nl * 256 + ((seg ^ (nl & 7)) << 4) + (kk & 7) * 2);
        *(__half*)(&g_w_img[jb][0][kc][off]) = hi;
        *(__half*)(&g_w_img[jb][1][kc][off]) = lo;
    }
}

// ---------------- seq / W_ih -> pre-swizzled GEMM1 images (bf16 hi/lo) --------------
__global__ __launch_bounds__(256) void a_prep(const float* __restrict__ seq) {
    int m = blockIdx.x;              // 0..32767 (= b*512 + t)
    int mblk = m >> 7;
    int row = m & 127;
    const float* src = seq + (size_t)m * Idim;
#pragma unroll
    for (int q = 0; q < 2; q++) {
        int k = q * 256 + threadIdx.x;
        float v = src[k];
        __nv_bfloat16 hi = __float2bfloat16(v);
        __nv_bfloat16 lo = __float2bfloat16(v - __bfloat162float(hi));
        int kc = k >> 6;
        int kk = k & 63;
        int seg = kk >> 3;
        uint32_t off = (uint32_t)(row * 128 + ((seg ^ (row & 7)) << 4) + (kk & 7) * 2);
        *(__nv_bfloat16*)(&g_a_img[0][mblk][kc][off]) = hi;
        *(__nv_bfloat16*)(&g_a_img[1][mblk][kc][off]) = lo;
    }
}
__global__ __launch_bounds__(256) void b_prep(const float* __restrict__ Wih) {
    int n = blockIdx.x;              // 0..4095
    int nblk = n >> 7;
    int row = n & 127;
    const float* src = Wih + (size_t)n * Idim;
#pragma unroll
    for (int q = 0; q < 2; q++) {
        int k = q * 256 + threadIdx.x;
        float v = src[k];
        __nv_bfloat16 hi = __float2bfloat16(v);
        __nv_bfloat16 lo = __float2bfloat16(v - __bfloat162float(hi));
        int kc = k >> 6;
        int kk = k & 63;
        int seg = kk >> 3;
        uint32_t off = (uint32_t)(row * 128 + ((seg ^ (row & 7)) << 4) + (kk & 7) * 2);
        *(__nv_bfloat16*)(&g_b_img[0][nblk][kc][off]) = hi;
        *(__nv_bfloat16*)(&g_b_img[1][nblk][kc][off]) = lo;
    }
}

// ---------------- GEMM1: HMMA split-bf16, bulk-DMA 3-stage pipeline (round-15) ------
#define G1_STG 65536                    // Ah 0 | Al 16384 | Bh 32768 | Bl 49152
#define G1_MBAR (3 * G1_STG)            // 196608
#define G1_SMEM (G1_MBAR + 64)

__global__ __launch_bounds__(256) void gemm1_mma(
    const float* __restrict__ bih, const float* __restrict__ bhh) {
    extern __shared__ unsigned char smem[];
    const uint32_t sb = smem_u32(smem);
    const uint32_t mb0 = sb + G1_MBAR;

    const int tid = threadIdx.x;
    const int lane = tid & 31;
    const int w = tid >> 5;
    const int mt = w & 3;
    const int nh = w >> 2;
    const int nblk = blockIdx.x;
    const int mblk = blockIdx.y;

    if (tid == 0) {
#pragma unroll
        for (int s = 0; s < 3; s++) mbar_init(mb0 + s * 8, 1);
    }
    __syncthreads();

    auto issue_chunk = [&](int kc) {
        int s = kc % 3;
        uint32_t dst = sb + s * G1_STG;
        uint32_t mb = mb0 + s * 8;
        mbar_expect(mb, 65536);
        bulk_g2s(dst,         &g_a_img[0][mblk][kc][0], 16384, mb);
        bulk_g2s(dst + 16384, &g_a_img[1][mblk][kc][0], 16384, mb);
        bulk_g2s(dst + 32768, &g_b_img[0][nblk][kc][0], 16384, mb);
        bulk_g2s(dst + 49152, &g_b_img[1][nblk][kc][0], 16384, mb);
    };
    if (tid == 0) { issue_chunk(0); issue_chunk(1); issue_chunk(2); }

    const int rowa = mt * 32 + (lane & 7) + ((lane >> 3) & 1) * 8;
    const int selA = (lane >> 4) & 1;
    const int xa = rowa & 7;
    const uint32_t a_base = (uint32_t)(rowa * 128);
    const int rowb = nh * 64 + (lane & 7) + ((lane >> 4) & 1) * 8;
    const int selB = (lane >> 3) & 1;
    const int xb = rowb & 7;
    const uint32_t b_base = (uint32_t)(32768 + rowb * 128);

    float C[2][8][4];
#pragma unroll
    for (int i = 0; i < 2; i++)
#pragma unroll
        for (int j = 0; j < 8; j++)
#pragma unroll
            for (int k = 0; k < 4; k++) C[i][j][k] = 0.f;

    for (int kc = 0; kc < 8; kc++) {
        mbar_wait(mb0 + (kc % 3) * 8, (kc / 3) & 1);
        uint32_t base = sb + (kc % 3) * G1_STG;
#pragma unroll
        for (int ks = 0; ks < 4; ks++) {
            uint32_t aoff = base + a_base + (uint32_t)((((2 * ks + selA) ^ xa)) << 4);
            uint32_t boff = base + b_base + (uint32_t)((((2 * ks + selB) ^ xb)) << 4);
            uint32_t ah0, ah1, ah2, ah3, ah4, ah5, ah6, ah7;
            uint32_t al0, al1, al2, al3, al4, al5, al6, al7;
            ldm_x4(ah0, ah1, ah2, ah3, aoff);
            ldm_x4(ah4, ah5, ah6, ah7, aoff + 2048);
            ldm_x4(al0, al1, al2, al3, aoff + 16384);
            ldm_x4(al4, al5, al6, al7, aoff + 16384 + 2048);
#pragma unroll
            for (int nt = 0; nt < 4; nt++) {
                uint32_t p0, p1, p2, p3, q0, q1, q2, q3;
                ldm_x4(p0, p1, p2, p3, boff + nt * 2048);
                ldm_x4(q0, q1, q2, q3, boff + 16384 + nt * 2048);
                mma_bf16(C[0][nt * 2 + 0], ah0, ah1, ah2, ah3, p0, p1);
                mma_bf16(C[0][nt * 2 + 1], ah0, ah1, ah2, ah3, p2, p3);
                mma_bf16(C[1][nt * 2 + 0], ah4, ah5, ah6, ah7, p0, p1);
                mma_bf16(C[1][nt * 2 + 1], ah4, ah5, ah6, ah7, p2, p3);
                mma_bf16(C[0][nt * 2 + 0], ah0, ah1, ah2, ah3, q0, q1);
                mma_bf16(C[0][nt * 2 + 1], ah0, ah1, ah2, ah3, q2, q3);
                mma_bf16(C[1][nt * 2 + 0], ah4, ah5, ah6, ah7, q0, q1);
                mma_bf16(C[1][nt * 2 + 1], ah4, ah5, ah6, ah7, q2, q3);
                mma_bf16(C[0][nt * 2 + 0], al0, al1, al2, al3, p0, p1);
                mma_bf16(C[0][nt * 2 + 1], al0, al1, al2, al3, p2, p3);
                mma_bf16(C[1][nt * 2 + 0], al4, al5, al6, al7, p0, p1);
                mma_bf16(C[1][nt * 2 + 1], al4, al5, al6, al7, p2, p3);
            }
        }
        __syncthreads();
        if (tid == 0 && kc + 3 < 8) issue_chunk(kc + 3);
    }

    {
        int g = lane >> 2, t2 = (lane & 3) * 2;
#pragma unroll
        for (int mi = 0; mi < 2; mi++) {
            int mrow = mblk * 128 + mt * 32 + mi * 16 + g;
            int b0 = mrow >> 9, t0 = mrow & 511;
            int mrow8 = mrow + 8;
            int b1 = mrow8 >> 9, t1 = mrow8 & 511;
            float* o0 = g_gates_x + ((size_t)t0 * Bdim + b0) * Gdim;
            float* o1 = g_gates_x + ((size_t)t1 * Bdim + b1) * Gdim;
#pragma unroll
            for (int f = 0; f < 8; f++) {
                int n = nblk * 128 + nh * 64 + f * 8 + t2;
                float bs0 = bih[n] + bhh[n];
                float bs1 = bih[n + 1] + bhh[n + 1];
                o0[n]     = C[mi][f][0] + bs0;
                o0[n + 1] = C[mi][f][1] + bs1;
                o1[n]     = C[mi][f][2] + bs0;
                o1[n + 1] = C[mi][f][3] + bs1;
            }
        }
    }
}

// ---------------- persistent HMMA recurrence (fp16 2-term, 4-stage h ring) ----------
// 128 CTAs (1/SM) x 512 thr. W fp16 hi + lo*2048 resident in smem; h single fp16
// plane streamed via bulk DMA into a 4-stage 16KB ring; per-chunk producer flags.
// Warp w: kq=w&3 (k-slices 2kq,2kq+1 per chunk), nh=(w>>2)&1 (cols nh*16..),
// mw=w>>3 (batches mw*32..). Per slice: 2 A-ldm.x4 + 2 B-ldm.x4, 8 MMAs (2 terms).
// Merge: gates = C0 + C1/2048.
#define OFF_W 0                          // [plane][kc][8192] = 131072 B
#define OFF_H 131072                     // 4 stages x 16384
#define OFF_PRE (OFF_H + 4 * 16384)      // 196608
#define PRE_SZ (64 * 36 * 4)             // 9216
#define OFF_MBAR (OFF_PRE + 2 * PRE_SZ)  // 215040 (4 h mbars + w mbar)
#define SMEM_BYTES (OFF_MBAR + 64)       // 215104

__global__ __launch_bounds__(512, 1) void lstm_persist(
    const int* __restrict__ lens, float* __restrict__ out) {
    extern __shared__ unsigned char smem[];
    const uint32_t sb = smem_u32(smem);
    float* pre0 = (float*)(smem + OFF_PRE);       // [64][36]
    float* pre1 = (float*)(smem + OFF_PRE + PRE_SZ);
    const uint32_t mb_h = sb + OFF_MBAR;          // 4 stage mbars, 8B apart
    const uint32_t mb_w = sb + OFF_MBAR + 32;

    const int tid = threadIdx.x;
    const int lane = tid & 31;
    const int w = tid >> 5;
    const int kq = w & 3;
    const int nh = (w >> 2) & 1;
    const int mw = w >> 3;
    const int jb = blockIdx.x;
    const int j0 = jb * 8;

    if (tid == 0) {
#pragma unroll
        for (int s = 0; s < 4; s++) mbar_init(mb_h + s * 8, 1);
        mbar_init(mb_w, 1);
    }
    __syncthreads();

    // ---- one-time: W slice (both planes) -> smem via 2 bulk copies
    if (tid == 0) {
        mbar_expect(mb_w, 131072);
        bulk_g2s(sb + OFF_W,         &g_w_img[jb][0][0][0], 65536, mb_w);
        bulk_g2s(sb + OFF_W + 65536, &g_w_img[jb][1][0][0], 65536, mb_w);
    }
    mbar_wait(mb_w, 0);

    // ---- per-lane fragment addressing (swizzle proven rounds 10-15)
    const int rowa = mw * 32 + (lane & 7) + ((lane >> 3) & 1) * 8;   // A row (batch)
    const int selA = (lane >> 4) & 1;
    const int xa = rowa & 7;
    const uint32_t a_base = (uint32_t)(rowa * 256);
    const int rowb = nh * 16 + (lane & 7) + ((lane >> 4) & 1) * 8;   // B row (gate col)
    const int selB = (lane >> 3) & 1;
    const int xb = rowb & 7;
    const uint32_t b_base = (uint32_t)(rowb * 256);

    // ---- persistent per-thread state (threads 0-63: b = tid)
    float cst[8];
#pragma unroll
    for (int q = 0; q < 8; q++) cst[q] = 0.0f;
    const int lb = (tid < 64) ? lens[tid] : 0;

    const int jc = j0 >> 7;
    const int sg = (j0 & 127) >> 3;

    for (int t = 0; t < Tdim; t++) {
        const int pp = t & 1;
        const unsigned tgt = 16u * (unsigned)t;

        // poll producer flag for chunk kc, then issue its bulk copy (4-stage ring)
        auto issue_chunk = [&](int kc) {
            while (*((volatile unsigned*)&g_cflag[kc]) < tgt) { }
            int n = t * 8 + kc;
            int s = n & 3;
            uint32_t mb = mb_h + s * 8;
            mbar_expect(mb, 16384);
            bulk_g2s(sb + OFF_H + s * 16384, &g_h_img[pp][kc][0], 16384, mb);
        };

        if (tid == 0) { issue_chunk(0); issue_chunk(1); issue_chunk(2); }

        // gates_x prefetch (threads 0-63, b = tid)
        float gx[32];
        if (tid < 64) {
            const float* gxb = g_gates_x + ((size_t)t * Bdim + tid) * Gdim + j0;
#pragma unroll
            for (int g = 0; g < 4; g++) {
                float4 v0 = *(const float4*)(gxb + g * Hdim);
                float4 v1 = *(const float4*)(gxb + g * Hdim + 4);
                gx[g * 8 + 0] = v0.x; gx[g * 8 + 1] = v0.y;
                gx[g * 8 + 2] = v0.z; gx[g * 8 + 3] = v0.w;
                gx[g * 8 + 4] = v1.x; gx[g * 8 + 5] = v1.y;
                gx[g * 8 + 6] = v1.z; gx[g * 8 + 7] = v1.w;
            }
        }

        // accumulators: [mt2][nt][4] per term (C0 = W_hi, C1 = W_lo*2048)
        float C0[2][2][4], C1[2][2][4];
#pragma unroll
        for (int i = 0; i < 2; i++)
#pragma unroll
            for (int j = 0; j < 2; j++)
#pragma unroll
                for (int k = 0; k < 4; k++) { C0[i][j][k] = 0.f; C1[i][j][k] = 0.f; }

        for (int kc = 0; kc < 8; kc++) {
            int n = t * 8 + kc;
            mbar_wait(mb_h + (n & 3) * 8, (n >> 2) & 1);

            uint32_t abase = sb + OFF_H + (n & 3) * 16384 + a_base;
            uint32_t bbase = sb + OFF_W + kc * 8192 + b_base;
#pragma unroll
            for (int s = 0; s < 2; s++) {
                int ks = kq * 2 + s;
                uint32_t aoff = abase + (uint32_t)((((2 * ks + selA) ^ xa)) << 4);
                uint32_t boff = bbase + (uint32_t)((((2 * ks + selB) ^ xb)) << 4);
                uint32_t a0, a1, a2, a3, a4, a5, a6, a7;   // A: m16 low, m16 high
                ldm_x4(a0, a1, a2, a3, aoff);
                ldm_x4(a4, a5, a6, a7, aoff + 4096);
                uint32_t p0, p1, p2, p3;          // B hi (n16)
                ldm_x4(p0, p1, p2, p3, boff);
                uint32_t q0, q1, q2, q3;          // B lo*2048
                ldm_x4(q0, q1, q2, q3, boff + 65536);

                mma_f16(C0[0][0], a0, a1, a2, a3, p0, p1);
                mma_f16(C0[0][1], a0, a1, a2, a3, p2, p3);
                mma_f16(C0[1][0], a4, a5, a6, a7, p0, p1);
                mma_f16(C0[1][1], a4, a5, a6, a7, p2, p3);
                mma_f16(C1[0][0], a0, a1, a2, a3, q0, q1);
                mma_f16(C1[0][1], a0, a1, a2, a3, q2, q3);
                mma_f16(C1[1][0], a4, a5, a6, a7, q0, q1);
                mma_f16(C1[1][1], a4, a5, a6, a7, q2, q3);
            }
            __syncthreads();                      // reads of stage n&3 retired
            if (tid == 0 && kc + 3 < 8) issue_chunk(kc + 3);
        }

        // ---- kq-merge (gates = C0 + C1/2048): kq<2 write, kq>=2 accumulate
        {
            const float ISC = 1.0f / 2048.0f;
            int g = lane >> 2, t2 = (lane & 3) * 2;
            float* dst = (kq & 1) ? pre1 : pre0;
            if (kq < 2) {
#pragma unroll
                for (int mt2 = 0; mt2 < 2; mt2++)
#pragma unroll
                    for (int nt = 0; nt < 2; nt++) {
                        float s0 = C0[mt2][nt][0] + C1[mt2][nt][0] * ISC;
                        float s1 = C0[mt2][nt][1] + C1[mt2][nt][1] * ISC;
                        float s2 = C0[mt2][nt][2] + C1[mt2][nt][2] * ISC;
                        float s3 = C0[mt2][nt][3] + C1[mt2][nt][3] * ISC;
                        int m = mw * 32 + mt2 * 16 + g;
                        int nn = nh * 16 + nt * 8 + t2;
                        *(float2*)&dst[m * 36 + nn]       = make_float2(s0, s1);
                        *(float2*)&dst[(m + 8) * 36 + nn] = make_float2(s2, s3);
                    }
            }
            __syncthreads();
            if (kq >= 2) {
#pragma unroll
                for (int mt2 = 0; mt2 < 2; mt2++)
#pragma unroll
                    for (int nt = 0; nt < 2; nt++) {
                        float s0 = C0[mt2][nt][0] + C1[mt2][nt][0] * ISC;
                        float s1 = C0[mt2][nt][1] + C1[mt2][nt][1] * ISC;
                        float s2 = C0[mt2][nt][2] + C1[mt2][nt][2] * ISC;
                        float s3 = C0[mt2][nt][3] + C1[mt2][nt][3] * ISC;
                        int m = mw * 32 + mt2 * 16 + g;
                        int nn = nh * 16 + nt * 8 + t2;
                        float2 a0 = *(float2*)&dst[m * 36 + nn];
                        float2 a1 = *(float2*)&dst[(m + 8) * 36 + nn];
                        *(float2*)&dst[m * 36 + nn]       = make_float2(a0.x + s0, a0.y + s1);
                        *(float2*)&dst[(m + 8) * 36 + nn] = make_float2(a1.x + s2, a1.y + s3);
                    }
            }
        }
        __syncthreads();

        // pointwise LSTM cell (threads 0-63, b = tid)
        if (tid < 64) {
            int b = tid;
            float hn[8];
            unsigned short hu[8];
#pragma unroll
            for (int jj = 0; jj < 8; jj++) {
                float xi = pre0[b * 36 + jj]      + pre1[b * 36 + jj]      + gx[jj];
                float xf = pre0[b * 36 + 8 + jj]  + pre1[b * 36 + 8 + jj]  + gx[8 + jj];
                float xg = pre0[b * 36 + 16 + jj] + pre1[b * 36 + 16 + jj] + gx[16 + jj];
                float xo = pre0[b * 36 + 24 + jj] + pre1[b * 36 + 24 + jj] + gx[24 + jj];
                float i_ = sigm_(xi), f_ = sigm_(xf), g_ = tanh_(xg), o_ = sigm_(xo);
                float cn = f_ * cst[jj] + i_ * g_;
                cst[jj] = cn;
                float h = o_ * tanh_(cn);
                hn[jj] = h;
                hu[jj] = __half_as_ushort(__float2half(h));
            }
            uint4 vh;
            vh.x = (uint32_t)hu[0] | ((uint32_t)hu[1] << 16);
            vh.y = (uint32_t)hu[2] | ((uint32_t)hu[3] << 16);
            vh.z = (uint32_t)hu[4] | ((uint32_t)hu[5] << 16);
            vh.w = (uint32_t)hu[6] | ((uint32_t)hu[7] << 16);

            int pp1 = pp ^ 1;
            uint32_t hoff = (uint32_t)(b * 256 + ((sg ^ (b & 7)) << 4));
            *(uint4*)(&g_h_img[pp1][jc][hoff]) = vh;

            if (lb > t) {
                float* ob = out + (size_t)b * Hdim + j0;
                *(float4*)(ob)     = make_float4(hn[0], hn[1], hn[2], hn[3]);
                *(float4*)(ob + 4) = make_float4(hn[4], hn[5], hn[6], hn[7]);
            }
            asm volatile("fence.proxy.async;" ::: "memory");
            __threadfence();                       // release h-image writes to L2
        }

        // signal: this CTA's slice of chunk jc for step t+1 is ready
        __syncthreads();
        if (tid == 0) {
            atomicAdd(&g_cflag[jc], 1u);
        }
    }
}

// ---------------- launch ------------------------------------------------------------
extern "C" void kernel_launch(void* const* d_in, const int* in_sizes, int n_in,
                              void* d_out, int out_size) {
    const float* seq   = (const float*)d_in[0];
    const int*   lensp = (const int*)d_in[1];
    const float* Wih   = (const float*)d_in[2];
    const float* Whh   = (const float*)d_in[3];
    const float* bih   = (const float*)d_in[4];
    const float* bhh   = (const float*)d_in[5];
    float* out = (float*)d_out;

    cudaFuncSetAttribute(lstm_persist,
                         cudaFuncAttributeMaxDynamicSharedMemorySize, SMEM_BYTES);
    cudaFuncSetAttribute(gemm1_mma,
                         cudaFuncAttributeMaxDynamicSharedMemorySize, G1_SMEM);

    init_state<<<256, 256>>>(out);
    w_prep<<<4096, 256>>>(Whh);
    a_prep<<<32768, 256>>>(seq);
    b_prep<<<4096, 256>>>(Wih);

    dim3 g1(Gdim / 128, (Bdim * Tdim) / 128);
    gemm1_mma<<<g1, 256, G1_SMEM>>>(bih, bhh);

    lstm_persist<<<NCTA, 512, SMEM_BYTES>>>(lensp, out);
}

// round 17
// speedup vs baseline: 2.5506x; 1.0714x over previous
#include <cuda_runtime.h>
#include <cuda_bf16.h>
#include <cuda_fp16.h>
#include <cstdint>

#define Bdim 64
#define Tdim 512
#define Idim 512
#define Hdim 1024
#define Gdim 4096
#define NCTA 128

typedef unsigned long long ull;

// ---------------- device globals (allocation-free scratch) ----------------------
__device__ float g_gates_x[(size_t)Tdim * Bdim * Gdim];          // [t][b][4096]
// pre-swizzled chunk images: row*pitch + ((seg ^ (row&7))<<4)
__device__ __align__(16) unsigned char g_h_img[2][8][16384];     // fp16 h [pp][kc][64 rows x 256B]
__device__ __align__(16) unsigned char g_w_img[NCTA][2][8][8192]; // fp16 W hi / lo*2048
__device__ unsigned g_cflag[8];                                  // per-chunk producer counters
// GEMM1 images: 128 rows x 64 k bf16 (pitch 128B) per chunk
__device__ __align__(16) unsigned char g_a_img[2][256][8][16384]; // [plane][mblk][kc]
__device__ __align__(16) unsigned char g_b_img[2][32][8][16384];  // [plane][nblk][kc]

// ---------------- helpers --------------------------------------------------------
__device__ __forceinline__ uint32_t smem_u32(const void* p) {
    uint32_t a;
    asm("{ .reg .u64 t; cvta.to.shared.u64 t, %1; cvt.u32.u64 %0, t; }" : "=r"(a) : "l"(p));
    return a;
}
__device__ __forceinline__ void mbar_init(uint32_t a, uint32_t cnt) {
    asm volatile("mbarrier.init.shared.b64 [%0], %1;" :: "r"(a), "r"(cnt) : "memory");
}
__device__ __forceinline__ void mbar_expect(uint32_t a, uint32_t tx) {
    asm volatile("mbarrier.arrive.expect_tx.shared.b64 _, [%0], %1;" :: "r"(a), "r"(tx) : "memory");
}
__device__ __forceinline__ void mbar_wait(uint32_t a, uint32_t parity) {
    asm volatile(
        "{\n\t.reg .pred P;\n\t"
        "WL_%=:\n\t"
        "mbarrier.try_wait.parity.acquire.cta.shared::cta.b64 P, [%0], %1, 0x989680;\n\t"
        "@P bra WD_%=;\n\t"
        "bra WL_%=;\n\t"
        "WD_%=:\n\t}"
        :: "r"(a), "r"(parity) : "memory");
}
__device__ __forceinline__ void bulk_g2s(uint32_t dst, const void* src, uint32_t bytes,
                                         uint32_t mbar) {
    asm volatile(
        "cp.async.bulk.shared::cta.global.mbarrier::complete_tx::bytes [%0], [%1], %2, [%3];"
        :: "r"(dst), "l"(src), "r"(bytes), "r"(mbar) : "memory");
}
__device__ __forceinline__ void ldm_x4(uint32_t& r0, uint32_t& r1, uint32_t& r2,
                                       uint32_t& r3, uint32_t addr) {
    asm volatile("ldmatrix.sync.aligned.m8n8.x4.shared.b16 {%0,%1,%2,%3}, [%4];"
                 : "=r"(r0), "=r"(r1), "=r"(r2), "=r"(r3) : "r"(addr));
}
__device__ __forceinline__ void mma_bf16(float* c, uint32_t a0, uint32_t a1,
                                         uint32_t a2, uint32_t a3,
                                         uint32_t b0, uint32_t b1) {
    asm volatile(
        "mma.sync.aligned.m16n8k16.row.col.f32.bf16.bf16.f32 "
        "{%0,%1,%2,%3}, {%4,%5,%6,%7}, {%8,%9}, {%0,%1,%2,%3};"
        : "+f"(c[0]), "+f"(c[1]), "+f"(c[2]), "+f"(c[3])
        : "r"(a0), "r"(a1), "r"(a2), "r"(a3), "r"(b0), "r"(b1));
}
__device__ __forceinline__ void mma_f16(float* c, uint32_t a0, uint32_t a1,
                                        uint32_t a2, uint32_t a3,
                                        uint32_t b0, uint32_t b1) {
    asm volatile(
        "mma.sync.aligned.m16n8k16.row.col.f32.f16.f16.f32 "
        "{%0,%1,%2,%3}, {%4,%5,%6,%7}, {%8,%9}, {%0,%1,%2,%3};"
        : "+f"(c[0]), "+f"(c[1]), "+f"(c[2]), "+f"(c[3])
        : "r"(a0), "r"(a1), "r"(a2), "r"(a3), "r"(b0), "r"(b1));
}
__device__ __forceinline__ float sigm_(float x) {
    return __fdividef(1.0f, 1.0f + __expf(-x));
}
__device__ __forceinline__ float tanh_(float x) {
    return 1.0f - __fdividef(2.0f, __expf(2.0f * x) + 1.0f);
}

// ---------------- init ------------------------------------------------------------
__global__ void init_state(float* __restrict__ out) {
    int i = blockIdx.x * blockDim.x + threadIdx.x;  // 65536 threads
    if (i < 32768) ((uint32_t*)g_h_img[0])[i] = 0u;  // zero pp=0 h image (128 KB)
    out[i] = 0.0f;
    if (i < 8) g_cflag[i] = 0u;
}

// ---------------- W_hh -> pre-swizzled fp16 hi / lo*2048 chunk images ---------------
__global__ __launch_bounds__(256) void w_prep(const float* __restrict__ Whh) {
    int bid = blockIdx.x;            // 4096 = 128 jb x 32 nl
    int jb = bid >> 5;
    int nl = bid & 31;
    int grow = (nl >> 3) * Hdim + jb * 8 + (nl & 7);
    const float* src = Whh + (size_t)grow * Hdim;
#pragma unroll
    for (int q = 0; q < 4; q++) {
        int k = q * 256 + threadIdx.x;
        float w = src[k];
        __half hi = __float2half(w);
        __half lo = __float2half((w - __half2float(hi)) * 2048.0f);
        int kc = k >> 7;
        int kk = k & 127;
        int seg = kk >> 3;
        uint32_t off = (uint32_t)(nl * 256 + ((seg ^ (nl & 7)) << 4) + (kk & 7) * 2);
        *(__half*)(&g_w_img[jb][0][kc][off]) = hi;
        *(__half*)(&g_w_img[jb][1][kc][off]) = lo;
    }
}

// ---------------- seq / W_ih -> pre-swizzled GEMM1 images (bf16 hi/lo) --------------
__global__ __launch_bounds__(256) void a_prep(const float* __restrict__ seq) {
    int m = blockIdx.x;              // 0..32767 (= b*512 + t)
    int mblk = m >> 7;
    int row = m & 127;
    const float* src = seq + (size_t)m * Idim;
#pragma unroll
    for (int q = 0; q < 2; q++) {
        int k = q * 256 + threadIdx.x;
        float v = src[k];
        __nv_bfloat16 hi = __float2bfloat16(v);
        __nv_bfloat16 lo = __float2bfloat16(v - __bfloat162float(hi));
        int kc = k >> 6;
        int kk = k & 63;
        int seg = kk >> 3;
        uint32_t off = (uint32_t)(row * 128 + ((seg ^ (row & 7)) << 4) + (kk & 7) * 2);
        *(__nv_bfloat16*)(&g_a_img[0][mblk][kc][off]) = hi;
        *(__nv_bfloat16*)(&g_a_img[1][mblk][kc][off]) = lo;
    }
}
__global__ __launch_bounds__(256) void b_prep(const float* __restrict__ Wih) {
    int n = blockIdx.x;              // 0..4095
    int nblk = n >> 7;
    int row = n & 127;
    const float* src = Wih + (size_t)n * Idim;
#pragma unroll
    for (int q = 0; q < 2; q++) {
        int k = q * 256 + threadIdx.x;
        float v = src[k];
        __nv_bfloat16 hi = __float2bfloat16(v);
        __nv_bfloat16 lo = __float2bfloat16(v - __bfloat162float(hi));
        int kc = k >> 6;
        int kk = k & 63;
        int seg = kk >> 3;
        uint32_t off = (uint32_t)(row * 128 + ((seg ^ (row & 7)) << 4) + (kk & 7) * 2);
        *(__nv_bfloat16*)(&g_b_img[0][nblk][kc][off]) = hi;
        *(__nv_bfloat16*)(&g_b_img[1][nblk][kc][off]) = lo;
    }
}

// ---------------- GEMM1: HMMA split-bf16, bulk-DMA 3-stage pipeline (round-15) ------
#define G1_STG 65536                    // Ah 0 | Al 16384 | Bh 32768 | Bl 49152
#define G1_MBAR (3 * G1_STG)            // 196608
#define G1_SMEM (G1_MBAR + 64)

__global__ __launch_bounds__(256) void gemm1_mma(
    const float* __restrict__ bih, const float* __restrict__ bhh) {
    extern __shared__ unsigned char smem[];
    const uint32_t sb = smem_u32(smem);
    const uint32_t mb0 = sb + G1_MBAR;

    const int tid = threadIdx.x;
    const int lane = tid & 31;
    const int w = tid >> 5;
    const int mt = w & 3;
    const int nh = w >> 2;
    const int nblk = blockIdx.x;
    const int mblk = blockIdx.y;

    if (tid == 0) {
#pragma unroll
        for (int s = 0; s < 3; s++) mbar_init(mb0 + s * 8, 1);
    }
    __syncthreads();

    auto issue_chunk = [&](int kc) {
        int s = kc % 3;
        uint32_t dst = sb + s * G1_STG;
        uint32_t mb = mb0 + s * 8;
        mbar_expect(mb, 65536);
        bulk_g2s(dst,         &g_a_img[0][mblk][kc][0], 16384, mb);
        bulk_g2s(dst + 16384, &g_a_img[1][mblk][kc][0], 16384, mb);
        bulk_g2s(dst + 32768, &g_b_img[0][nblk][kc][0], 16384, mb);
        bulk_g2s(dst + 49152, &g_b_img[1][nblk][kc][0], 16384, mb);
    };
    if (tid == 0) { issue_chunk(0); issue_chunk(1); issue_chunk(2); }

    const int rowa = mt * 32 + (lane & 7) + ((lane >> 3) & 1) * 8;
    const int selA = (lane >> 4) & 1;
    const int xa = rowa & 7;
    const uint32_t a_base = (uint32_t)(rowa * 128);
    const int rowb = nh * 64 + (lane & 7) + ((lane >> 4) & 1) * 8;
    const int selB = (lane >> 3) & 1;
    const int xb = rowb & 7;
    const uint32_t b_base = (uint32_t)(32768 + rowb * 128);

    float C[2][8][4];
#pragma unroll
    for (int i = 0; i < 2; i++)
#pragma unroll
        for (int j = 0; j < 8; j++)
#pragma unroll
            for (int k = 0; k < 4; k++) C[i][j][k] = 0.f;

    for (int kc = 0; kc < 8; kc++) {
        mbar_wait(mb0 + (kc % 3) * 8, (kc / 3) & 1);
        uint32_t base = sb + (kc % 3) * G1_STG;
#pragma unroll
        for (int ks = 0; ks < 4; ks++) {
            uint32_t aoff = base + a_base + (uint32_t)((((2 * ks + selA) ^ xa)) << 4);
            uint32_t boff = base + b_base + (uint32_t)((((2 * ks + selB) ^ xb)) << 4);
            uint32_t ah0, ah1, ah2, ah3, ah4, ah5, ah6, ah7;
            uint32_t al0, al1, al2, al3, al4, al5, al6, al7;
            ldm_x4(ah0, ah1, ah2, ah3, aoff);
            ldm_x4(ah4, ah5, ah6, ah7, aoff + 2048);
            ldm_x4(al0, al1, al2, al3, aoff + 16384);
            ldm_x4(al4, al5, al6, al7, aoff + 16384 + 2048);
#pragma unroll
            for (int nt = 0; nt < 4; nt++) {
                uint32_t p0, p1, p2, p3, q0, q1, q2, q3;
                ldm_x4(p0, p1, p2, p3, boff + nt * 2048);
                ldm_x4(q0, q1, q2, q3, boff + 16384 + nt * 2048);
                mma_bf16(C[0][nt * 2 + 0], ah0, ah1, ah2, ah3, p0, p1);
                mma_bf16(C[0][nt * 2 + 1], ah0, ah1, ah2, ah3, p2, p3);
                mma_bf16(C[1][nt * 2 + 0], ah4, ah5, ah6, ah7, p0, p1);
                mma_bf16(C[1][nt * 2 + 1], ah4, ah5, ah6, ah7, p2, p3);
                mma_bf16(C[0][nt * 2 + 0], ah0, ah1, ah2, ah3, q0, q1);
                mma_bf16(C[0][nt * 2 + 1], ah0, ah1, ah2, ah3, q2, q3);
                mma_bf16(C[1][nt * 2 + 0], ah4, ah5, ah6, ah7, q0, q1);
                mma_bf16(C[1][nt * 2 + 1], ah4, ah5, ah6, ah7, q2, q3);
                mma_bf16(C[0][nt * 2 + 0], al0, al1, al2, al3, p0, p1);
                mma_bf16(C[0][nt * 2 + 1], al0, al1, al2, al3, p2, p3);
                mma_bf16(C[1][nt * 2 + 0], al4, al5, al6, al7, p0, p1);
                mma_bf16(C[1][nt * 2 + 1], al4, al5, al6, al7, p2, p3);
            }
        }
        __syncthreads();
        if (tid == 0 && kc + 3 < 8) issue_chunk(kc + 3);
    }

    {
        int g = lane >> 2, t2 = (lane & 3) * 2;
#pragma unroll
        for (int mi = 0; mi < 2; mi++) {
            int mrow = mblk * 128 + mt * 32 + mi * 16 + g;
            int b0 = mrow >> 9, t0 = mrow & 511;
            int mrow8 = mrow + 8;
            int b1 = mrow8 >> 9, t1 = mrow8 & 511;
            float* o0 = g_gates_x + ((size_t)t0 * Bdim + b0) * Gdim;
            float* o1 = g_gates_x + ((size_t)t1 * Bdim + b1) * Gdim;
#pragma unroll
            for (int f = 0; f < 8; f++) {
                int n = nblk * 128 + nh * 64 + f * 8 + t2;
                float bs0 = bih[n] + bhh[n];
                float bs1 = bih[n + 1] + bhh[n + 1];
                o0[n]     = C[mi][f][0] + bs0;
                o0[n + 1] = C[mi][f][1] + bs1;
                o1[n]     = C[mi][f][2] + bs0;
                o1[n + 1] = C[mi][f][3] + bs1;
            }
        }
    }
}

// ---------------- persistent HMMA recurrence (fp16 2-term, 4 BIG chunks) ------------
// 128 CTAs (1/SM) x 512 thr. W fp16 hi + lo*2048 resident in smem. h streamed in
// FOUR 256-col chunks (32 KB, one bulk each) through a 2-stage 64KB ring -> only
// 4 mbar_waits + 4 __syncthreads per step. Chunk C produced by CTAs [32C,32C+32);
// consumer polls g_cflag[C] >= 32*t. Warp w: kq=w&3 owns 4 k16-slices per big chunk;
// nh=(w>>2)&1 (cols nh*16..); mw=w>>3 (batches mw*32..). gates = C0 + C1/2048.
#define OFF_W 0                          // [plane][kc][8192] = 131072 B
#define OFF_H 131072                     // 2 stages x 32768
#define OFF_PRE (OFF_H + 2 * 32768)      // 196608
#define PRE_SZ (64 * 36 * 4)             // 9216
#define OFF_MBAR (OFF_PRE + 2 * PRE_SZ)  // 215040 (2 h mbars + w mbar)
#define SMEM_BYTES (OFF_MBAR + 64)       // 215104

__global__ __launch_bounds__(512, 1) void lstm_persist(
    const int* __restrict__ lens, float* __restrict__ out) {
    extern __shared__ unsigned char smem[];
    const uint32_t sb = smem_u32(smem);
    float* pre0 = (float*)(smem + OFF_PRE);       // [64][36]
    float* pre1 = (float*)(smem + OFF_PRE + PRE_SZ);
    const uint32_t mb_h = sb + OFF_MBAR;          // 2 stage mbars, 8B apart
    const uint32_t mb_w = sb + OFF_MBAR + 16;

    const int tid = threadIdx.x;
    const int lane = tid & 31;
    const int w = tid >> 5;
    const int kq = w & 3;
    const int nh = (w >> 2) & 1;
    const int mw = w >> 3;
    const int jb = blockIdx.x;
    const int j0 = jb * 8;

    if (tid == 0) {
        mbar_init(mb_h, 1);
        mbar_init(mb_h + 8, 1);
        mbar_init(mb_w, 1);
    }
    __syncthreads();

    // ---- one-time: W slice (both planes) -> smem via 2 bulk copies
    if (tid == 0) {
        mbar_expect(mb_w, 131072);
        bulk_g2s(sb + OFF_W,         &g_w_img[jb][0][0][0], 65536, mb_w);
        bulk_g2s(sb + OFF_W + 65536, &g_w_img[jb][1][0][0], 65536, mb_w);
    }
    mbar_wait(mb_w, 0);

    // ---- per-lane fragment addressing (swizzle proven rounds 10-16)
    const int rowa = mw * 32 + (lane & 7) + ((lane >> 3) & 1) * 8;   // A row (batch)
    const int selA = (lane >> 4) & 1;
    const int xa = rowa & 7;
    const uint32_t a_base = (uint32_t)(rowa * 256);
    const int rowb = nh * 16 + (lane & 7) + ((lane >> 4) & 1) * 8;   // B row (gate col)
    const int selB = (lane >> 3) & 1;
    const int xb = rowb & 7;
    const uint32_t b_base = (uint32_t)(rowb * 256);

    // ---- persistent per-thread state (threads 0-63: b = tid)
    float cst[8];
#pragma unroll
    for (int q = 0; q < 8; q++) cst[q] = 0.0f;
    const int lb = (tid < 64) ? lens[tid] : 0;

    const int jc = j0 >> 7;            // this CTA's 128-col h sub-chunk
    const int jc2 = jb >> 5;           // this CTA's 256-col flag index
    const int sg = (j0 & 127) >> 3;

    for (int t = 0; t < Tdim; t++) {
        const int pp = t & 1;
        const unsigned tgt = 32u * (unsigned)t;

        // poll producer flag for big chunk C (cols 256C..), then one 32KB bulk
        auto issue_chunk = [&](int C) {
            while (*((volatile unsigned*)&g_cflag[C]) < tgt) { }
            int n = t * 4 + C;
            int s = n & 1;
            uint32_t mb = mb_h + s * 8;
            mbar_expect(mb, 32768);
            bulk_g2s(sb + OFF_H + s * 32768, &g_h_img[pp][2 * C][0], 32768, mb);
        };

        if (tid == 0) { issue_chunk(0); issue_chunk(1); }

        // gates_x prefetch (threads 0-63, b = tid)
        float gx[32];
        if (tid < 64) {
            const float* gxb = g_gates_x + ((size_t)t * Bdim + tid) * Gdim + j0;
#pragma unroll
            for (int g = 0; g < 4; g++) {
                float4 v0 = *(const float4*)(gxb + g * Hdim);
                float4 v1 = *(const float4*)(gxb + g * Hdim + 4);
                gx[g * 8 + 0] = v0.x; gx[g * 8 + 1] = v0.y;
                gx[g * 8 + 2] = v0.z; gx[g * 8 + 3] = v0.w;
                gx[g * 8 + 4] = v1.x; gx[g * 8 + 5] = v1.y;
                gx[g * 8 + 6] = v1.z; gx[g * 8 + 7] = v1.w;
            }
        }

        // accumulators: [mt2][nt][4] per term (C0 = W_hi, C1 = W_lo*2048)
        float C0[2][2][4], C1[2][2][4];
#pragma unroll
        for (int i = 0; i < 2; i++)
#pragma unroll
            for (int j = 0; j < 2; j++)
#pragma unroll
                for (int k = 0; k < 4; k++) { C0[i][j][k] = 0.f; C1[i][j][k] = 0.f; }

        for (int C = 0; C < 4; C++) {
            int n = t * 4 + C;
            mbar_wait(mb_h + (n & 1) * 8, (n >> 1) & 1);

            uint32_t stg = sb + OFF_H + (n & 1) * 32768;
#pragma unroll
            for (int s = 0; s < 4; s++) {
                int ks = kq * 4 + s;          // 0..15 within big chunk
                int sub = ks >> 3;            // 128-col sub-chunk
                int ksl = ks & 7;
                uint32_t aoff = stg + sub * 16384 + a_base
                              + (uint32_t)((((2 * ksl + selA) ^ xa)) << 4);
                uint32_t boff = sb + OFF_W + (2 * C + sub) * 8192 + b_base
                              + (uint32_t)((((2 * ksl + selB) ^ xb)) << 4);
                uint32_t a0, a1, a2, a3, a4, a5, a6, a7;   // A: m16 low, m16 high
                ldm_x4(a0, a1, a2, a3, aoff);
                ldm_x4(a4, a5, a6, a7, aoff + 4096);
                uint32_t p0, p1, p2, p3;          // B hi (n16)
                ldm_x4(p0, p1, p2, p3, boff);
                uint32_t q0, q1, q2, q3;          // B lo*2048
                ldm_x4(q0, q1, q2, q3, boff + 65536);

                mma_f16(C0[0][0], a0, a1, a2, a3, p0, p1);
                mma_f16(C0[0][1], a0, a1, a2, a3, p2, p3);
                mma_f16(C0[1][0], a4, a5, a6, a7, p0, p1);
                mma_f16(C0[1][1], a4, a5, a6, a7, p2, p3);
                mma_f16(C1[0][0], a0, a1, a2, a3, q0, q1);
                mma_f16(C1[0][1], a0, a1, a2, a3, q2, q3);
                mma_f16(C1[1][0], a4, a5, a6, a7, q0, q1);
                mma_f16(C1[1][1], a4, a5, a6, a7, q2, q3);
            }
            __syncthreads();                      // reads of stage n&1 retired
            if (tid == 0 && C + 2 < 4) issue_chunk(C + 2);
        }

        // ---- kq-merge (gates = C0 + C1/2048): kq<2 write, kq>=2 accumulate
        {
            const float ISC = 1.0f / 2048.0f;
            int g = lane >> 2, t2 = (lane & 3) * 2;
            float* dst = (kq & 1) ? pre1 : pre0;
            if (kq < 2) {
#pragma unroll
                for (int mt2 = 0; mt2 < 2; mt2++)
#pragma unroll
                    for (int nt = 0; nt < 2; nt++) {
                        float s0 = C0[mt2][nt][0] + C1[mt2][nt][0] * ISC;
                        float s1 = C0[mt2][nt][1] + C1[mt2][nt][1] * ISC;
                        float s2 = C0[mt2][nt][2] + C1[mt2][nt][2] * ISC;
                        float s3 = C0[mt2][nt][3] + C1[mt2][nt][3] * ISC;
                        int m = mw * 32 + mt2 * 16 + g;
                        int nn = nh * 16 + nt * 8 + t2;
                        *(float2*)&dst[m * 36 + nn]       = make_float2(s0, s1);
                        *(float2*)&dst[(m + 8) * 36 + nn] = make_float2(s2, s3);
                    }
            }
            __syncthreads();
            if (kq >= 2) {
#pragma unroll
                for (int mt2 = 0; mt2 < 2; mt2++)
#pragma unroll
                    for (int nt = 0; nt < 2; nt++) {
                        float s0 = C0[mt2][nt][0] + C1[mt2][nt][0] * ISC;
                        float s1 = C0[mt2][nt][1] + C1[mt2][nt][1] * ISC;
                        float s2 = C0[mt2][nt][2] + C1[mt2][nt][2] * ISC;
                        float s3 = C0[mt2][nt][3] + C1[mt2][nt][3] * ISC;
                        int m = mw * 32 + mt2 * 16 + g;
                        int nn = nh * 16 + nt * 8 + t2;
                        float2 a0 = *(float2*)&dst[m * 36 + nn];
                        float2 a1 = *(float2*)&dst[(m + 8) * 36 + nn];
                        *(float2*)&dst[m * 36 + nn]       = make_float2(a0.x + s0, a0.y + s1);
                        *(float2*)&dst[(m + 8) * 36 + nn] = make_float2(a1.x + s2, a1.y + s3);
                    }
            }
        }
        __syncthreads();

        // pointwise LSTM cell (threads 0-63, b = tid)
        if (tid < 64) {
            int b = tid;
            float hn[8];
            unsigned short hu[8];
#pragma unroll
            for (int jj = 0; jj < 8; jj++) {
                float xi = pre0[b * 36 + jj]      + pre1[b * 36 + jj]      + gx[jj];
                float xf = pre0[b * 36 + 8 + jj]  + pre1[b * 36 + 8 + jj]  + gx[8 + jj];
                float xg = pre0[b * 36 + 16 + jj] + pre1[b * 36 + 16 + jj] + gx[16 + jj];
                float xo = pre0[b * 36 + 24 + jj] + pre1[b * 36 + 24 + jj] + gx[24 + jj];
                float i_ = sigm_(xi), f_ = sigm_(xf), g_ = tanh_(xg), o_ = sigm_(xo);
                float cn = f_ * cst[jj] + i_ * g_;
                cst[jj] = cn;
                float h = o_ * tanh_(cn);
                hn[jj] = h;
                hu[jj] = __half_as_ushort(__float2half(h));
            }
            uint4 vh;
            vh.x = (uint32_t)hu[0] | ((uint32_t)hu[1] << 16);
            vh.y = (uint32_t)hu[2] | ((uint32_t)hu[3] << 16);
            vh.z = (uint32_t)hu[4] | ((uint32_t)hu[5] << 16);
            vh.w = (uint32_t)hu[6] | ((uint32_t)hu[7] << 16);

            int pp1 = pp ^ 1;
            uint32_t hoff = (uint32_t)(b * 256 + ((sg ^ (b & 7)) << 4));
            *(uint4*)(&g_h_img[pp1][jc][hoff]) = vh;

            if (lb > t) {
                float* ob = out + (size_t)b * Hdim + j0;
                *(float4*)(ob)     = make_float4(hn[0], hn[1], hn[2], hn[3]);
                *(float4*)(ob + 4) = make_float4(hn[4], hn[5], hn[6], hn[7]);
            }
            asm volatile("fence.proxy.async;" ::: "memory");
            __threadfence();                       // release h-image writes to L2
        }

        // signal: this CTA's slice of big chunk jc2 for step t+1 is ready
        __syncthreads();
        if (tid == 0) {
            atomicAdd(&g_cflag[jc2], 1u);
        }
    }
}

// ---------------- launch ------------------------------------------------------------
extern "C" void kernel_launch(void* const* d_in, const int* in_sizes, int n_in,
                              void* d_out, int out_size) {
    const float* seq   = (const float*)d_in[0];
    const int*   lensp = (const int*)d_in[1];
    const float* Wih   = (const float*)d_in[2];
    const float* Whh   = (const float*)d_in[3];
    const float* bih   = (const float*)d_in[4];
    const float* bhh   = (const float*)d_in[5];
    float* out = (float*)d_out;

    cudaFuncSetAttribute(lstm_persist,
                         cudaFuncAttributeMaxDynamicSharedMemorySize, SMEM_BYTES);
    cudaFuncSetAttribute(gemm1_mma,
                         cudaFuncAttributeMaxDynamicSharedMemorySize, G1_SMEM);

    init_state<<<256, 256>>>(out);
    w_prep<<<4096, 256>>>(Whh);
    a_prep<<<32768, 256>>>(seq);
    b_prep<<<4096, 256>>>(Wih);

    dim3 g1(Gdim / 128, (Bdim * Tdim) / 128);
    gemm1_mma<<<g1, 256, G1_SMEM>>>(bih, bhh);

    lstm_persist<<<NCTA, 512, SMEM_BYTES>>>(lensp, out);
}